// round 1
// baseline (speedup 1.0000x reference)
#include <cuda_runtime.h>
#include <cuda_bf16.h>

// Problem constants
#define NB 4
#define NR 64
#define NC 64
#define NSEQ (NB*NR*NC)     // 16384
#define SLEN 32
#define HD 128              // hidden == embed dim
#define NROWS (NSEQ*SLEN)   // 524288 rows for layer-1 input projection

// ---------------- device scratch (no allocation allowed) ----------------
__device__ float g_pre1[(size_t)NROWS * HD];   // 256 MB: layer1 input projection
__device__ float g_h[(size_t)NSEQ * HD];       // 8 MB: final top-layer hidden
__device__ float g_u[NSEQ];
__device__ float g_v[NSEQ];

// =========================================================================
// Kernel 1: pre1[row][h] = embed[x[row]] @ Wi1^T + bi1   (row = n*S + t)
// CTA tile: 128 rows x 128 h, 256 threads, 8x8 per thread.
// =========================================================================
#define PROJ_SMEM ((16384 + 128*132) * 4)

__global__ void __launch_bounds__(256, 1) proj1_kernel(
    const int* __restrict__ x, const float* __restrict__ embed,
    const float* __restrict__ W_ih, const float* __restrict__ b_ih)
{
    extern __shared__ float sm[];
    float* As = sm;            // [128 rows][128 e]  row-major
    float* Ws = sm + 16384;    // [128 e][132 pitch] = Wi1^T (Ws[e][h] = Wi1[h][e])

    const int tid = threadIdx.x;
    const int rowBase = blockIdx.x * 128;

    // Load Wi1 transposed into smem (coalesced gmem read; one-time STS conflicts OK)
    for (int i = tid; i < 16384; i += 256) {
        int h = i >> 7, e = i & 127;
        Ws[e * 132 + h] = W_ih[i];           // layer 0
    }
    // Gather embedding rows (float4 coalesced)
    for (int i = tid; i < 128 * 32; i += 256) {
        int r = i >> 5, ec = i & 31;
        int token = x[rowBase + r];
        float4 v = ((const float4*)embed)[token * 32 + ec];
        ((float4*)As)[r * 32 + ec] = v;
    }
    __syncthreads();

    const int tx = tid & 15, ty = tid >> 4;
    const int r0 = ty * 8, h0 = tx * 8;

    float bias[8];
#pragma unroll
    for (int j = 0; j < 8; j++) bias[j] = b_ih[h0 + j];

    float acc[8][8];
#pragma unroll
    for (int i = 0; i < 8; i++)
#pragma unroll
        for (int j = 0; j < 8; j++) acc[i][j] = bias[j];

#pragma unroll 4
    for (int k = 0; k < 128; k++) {
        float4 b0 = *(const float4*)(Ws + k * 132 + h0);
        float4 b1 = *(const float4*)(Ws + k * 132 + h0 + 4);
        float bb[8] = {b0.x, b0.y, b0.z, b0.w, b1.x, b1.y, b1.z, b1.w};
        float a[8];
#pragma unroll
        for (int i = 0; i < 8; i++) a[i] = As[(r0 + i) * 128 + k];
#pragma unroll
        for (int i = 0; i < 8; i++)
#pragma unroll
            for (int j = 0; j < 8; j++)
                acc[i][j] = fmaf(a[i], bb[j], acc[i][j]);
    }

#pragma unroll
    for (int i = 0; i < 8; i++) {
        float* o = g_pre1 + (size_t)(rowBase + r0 + i) * 128 + h0;
        *(float4*)(o)     = make_float4(acc[i][0], acc[i][1], acc[i][2], acc[i][3]);
        *(float4*)(o + 4) = make_float4(acc[i][4], acc[i][5], acc[i][6], acc[i][7]);
    }
}

// =========================================================================
// Kernel 2: fused 2-layer recurrent scan.
//   h1_t = relu(pre1_t + Wh1 h1 + bh1)
//   h2_t = relu(Wi2 h1_t + bi2 + Wh2 h2 + bh2)
// CTA: 16 sequences, 256 threads (thread = 8 h-dims x 1 seq).
// SMEM: 3 transposed 128x128 weight mats + 2 hidden-state arrays [128][17].
// =========================================================================
#define HS_PITCH 17
#define SCAN_SMEM ((3 * 16384 + 2 * 128 * HS_PITCH) * 4)

__device__ __forceinline__ void gemv8(const float* __restrict__ WT,
                                      const float* __restrict__ hs,
                                      int h0, int s, float acc[8])
{
#pragma unroll 8
    for (int k = 0; k < 128; k++) {
        float4 w0 = *(const float4*)(WT + k * 128 + h0);
        float4 w1 = *(const float4*)(WT + k * 128 + h0 + 4);
        float hv = hs[k * HS_PITCH + s];
        acc[0] = fmaf(w0.x, hv, acc[0]);
        acc[1] = fmaf(w0.y, hv, acc[1]);
        acc[2] = fmaf(w0.z, hv, acc[2]);
        acc[3] = fmaf(w0.w, hv, acc[3]);
        acc[4] = fmaf(w1.x, hv, acc[4]);
        acc[5] = fmaf(w1.y, hv, acc[5]);
        acc[6] = fmaf(w1.z, hv, acc[6]);
        acc[7] = fmaf(w1.w, hv, acc[7]);
    }
}

__global__ void __launch_bounds__(256, 1) scan_kernel(
    const float* __restrict__ W_ih, const float* __restrict__ W_hh,
    const float* __restrict__ b_ih, const float* __restrict__ b_hh)
{
    extern __shared__ float sm[];
    float* W1T = sm;             // Wh (layer0) transposed [k][h]
    float* WiT = sm + 16384;     // W_ih (layer1) transposed
    float* W2T = sm + 32768;     // W_hh (layer1) transposed
    float* h1s = sm + 49152;                 // [128][HS_PITCH]
    float* h2s = h1s + 128 * HS_PITCH;

    const int tid = threadIdx.x;

    for (int i = tid; i < 16384; i += 256) {
        int h = i >> 7, k = i & 127;
        W1T[k * 128 + h] = W_hh[i];
        WiT[k * 128 + h] = W_ih[16384 + i];
        W2T[k * 128 + h] = W_hh[16384 + i];
    }
    for (int i = tid; i < 128 * HS_PITCH; i += 256) { h1s[i] = 0.f; h2s[i] = 0.f; }

    const int hx = tid & 15, s = tid >> 4;
    const int h0 = hx * 8;
    const int seq = blockIdx.x * 16 + s;

    float b1[8], b2[8];
#pragma unroll
    for (int j = 0; j < 8; j++) {
        b1[j] = b_hh[h0 + j];
        b2[j] = b_ih[128 + h0 + j] + b_hh[128 + h0 + j];
    }
    __syncthreads();

    const float* pre_base = g_pre1 + (size_t)seq * SLEN * 128 + h0;

    for (int t = 0; t < SLEN; t++) {
        // ---- Layer 1 ----
        float acc[8];
        const float* p = pre_base + t * 128;
        float4 p0 = *(const float4*)p;
        float4 p1 = *(const float4*)(p + 4);
        acc[0] = p0.x; acc[1] = p0.y; acc[2] = p0.z; acc[3] = p0.w;
        acc[4] = p1.x; acc[5] = p1.y; acc[6] = p1.z; acc[7] = p1.w;
        gemv8(W1T, h1s, h0, s, acc);
        __syncthreads();                       // all reads of old h1s done
#pragma unroll
        for (int j = 0; j < 8; j++)
            h1s[(h0 + j) * HS_PITCH + s] = fmaxf(acc[j] + b1[j], 0.f);
        __syncthreads();                       // new h1s visible

        // ---- Layer 2 ----
        float acc2[8];
#pragma unroll
        for (int j = 0; j < 8; j++) acc2[j] = b2[j];
        gemv8(WiT, h1s, h0, s, acc2);
        gemv8(W2T, h2s, h0, s, acc2);
        __syncthreads();                       // all reads of old h2s done
        if (t == SLEN - 1) {
            float r[8];
#pragma unroll
            for (int j = 0; j < 8; j++) r[j] = fmaxf(acc2[j], 0.f);
            float* o = g_h + (size_t)seq * 128 + h0;
            *(float4*)(o)     = make_float4(r[0], r[1], r[2], r[3]);
            *(float4*)(o + 4) = make_float4(r[4], r[5], r[6], r[7]);
        }
#pragma unroll
        for (int j = 0; j < 8; j++)
            h2s[(h0 + j) * HS_PITCH + s] = fmaxf(acc2[j], 0.f);
        __syncthreads();
    }
}

// =========================================================================
// Kernel 3a: u[n] = w1.h[n], v[n] = w2.h[n]   (one warp per sequence)
// =========================================================================
__global__ void reduce1_kernel(const float* __restrict__ predW)
{
    int gwarp = (blockIdx.x * blockDim.x + threadIdx.x) >> 5;
    int lane = threadIdx.x & 31;
    if (gwarp >= NSEQ) return;
    const float* hr = g_h + (size_t)gwarp * 128;
    float su = 0.f, sv = 0.f;
#pragma unroll
    for (int i = 0; i < 4; i++) {
        int idx = lane + 32 * i;
        float hv = hr[idx];
        su += hv * predW[idx];
        sv += hv * predW[128 + idx];
    }
#pragma unroll
    for (int o = 16; o; o >>= 1) {
        su += __shfl_xor_sync(0xffffffffu, su, o);
        sv += __shfl_xor_sync(0xffffffffu, sv, o);
    }
    if (lane == 0) { g_u[gwarp] = su; g_v[gwarp] = sv; }
}

// =========================================================================
// Kernel 3b: out[b,r,c] = u - 2v + rowsum(v) + colsum(v) + pred_b
// One CTA per batch element.
// =========================================================================
__global__ void reduce2_kernel(const float* __restrict__ pred_b,
                               float* __restrict__ out)
{
    __shared__ float vs[NR * NC];
    __shared__ float RS[NR], CS[NC];
    const int b = blockIdx.x, tid = threadIdx.x;

    for (int i = tid; i < NR * NC; i += 256) vs[i] = g_v[b * NR * NC + i];
    __syncthreads();
    if (tid < NR) {
        float sr = 0.f;
        for (int c = 0; c < NC; c++) sr += vs[tid * NC + c];
        RS[tid] = sr;
    } else if (tid < NR + NC) {
        int c = tid - NR;
        float sc = 0.f;
        for (int r = 0; r < NR; r++) sc += vs[r * NC + c];
        CS[c] = sc;
    }
    __syncthreads();
    float pb = pred_b[0];
    for (int i = tid; i < NR * NC; i += 256) {
        int r = i >> 6, c = i & 63;
        out[b * NR * NC + i] =
            g_u[b * NR * NC + i] - 2.f * vs[i] + RS[r] + CS[c] + pb;
    }
}

// =========================================================================
extern "C" void kernel_launch(void* const* d_in, const int* in_sizes, int n_in,
                              void* d_out, int out_size)
{
    const int*   x      = (const int*)  d_in[0];
    const float* embed  = (const float*)d_in[1];
    const float* W_ih   = (const float*)d_in[2];
    const float* W_hh   = (const float*)d_in[3];
    const float* b_ih   = (const float*)d_in[4];
    const float* b_hh   = (const float*)d_in[5];
    const float* pred_W = (const float*)d_in[6];
    const float* pred_b = (const float*)d_in[7];
    float* out = (float*)d_out;

    cudaFuncSetAttribute(proj1_kernel, cudaFuncAttributeMaxDynamicSharedMemorySize, PROJ_SMEM);
    cudaFuncSetAttribute(scan_kernel,  cudaFuncAttributeMaxDynamicSharedMemorySize, SCAN_SMEM);

    proj1_kernel<<<NROWS / 128, 256, PROJ_SMEM>>>(x, embed, W_ih, b_ih);
    scan_kernel<<<NSEQ / 16, 256, SCAN_SMEM>>>(W_ih, W_hh, b_ih, b_hh);
    reduce1_kernel<<<NSEQ / 8, 256>>>(pred_W);
    reduce2_kernel<<<NB, 256>>>(pred_b, out);
}

// round 2
// speedup vs baseline: 1.5904x; 1.5904x over previous
#include <cuda_runtime.h>
#include <cuda_bf16.h>

// Problem constants
#define NB 4
#define NR 64
#define NC 64
#define NSEQ (NB*NR*NC)     // 16384
#define SLEN 32
#define HD 128
#define NROWS (NSEQ*SLEN)   // 524288

typedef unsigned long long ull;

// ---------------- device scratch (no allocation allowed) ----------------
__device__ float g_pre1[(size_t)NROWS * HD];   // 256 MB
__device__ float g_h[(size_t)NSEQ * HD];       // 8 MB
__device__ float g_u[NSEQ];
__device__ float g_v[NSEQ];

// ---------------- f32x2 helpers (sm_103a packed fp32) -------------------
__device__ __forceinline__ ull pack2(float lo, float hi) {
    ull r; asm("mov.b64 %0, {%1, %2};" : "=l"(r) : "f"(lo), "f"(hi)); return r;
}
__device__ __forceinline__ ull ffma2(ull a, ull b, ull c) {
    ull d; asm("fma.rn.f32x2 %0, %1, %2, %3;" : "=l"(d) : "l"(a), "l"(b), "l"(c)); return d;
}
__device__ __forceinline__ ull add2(ull a, ull b) {
    ull d; asm("add.rn.f32x2 %0, %1, %2;" : "=l"(d) : "l"(a), "l"(b)); return d;
}
__device__ __forceinline__ float2 unpack2(ull v) {
    float2 f; asm("mov.b64 {%0, %1}, %2;" : "=f"(f.x), "=f"(f.y) : "l"(v)); return f;
}

// =========================================================================
// Kernel 1: pre1[row][h] = embed[x[row]] @ Wi1^T + bi1   (row = n*S + t)
// 128x128 tile, 256 threads, 8 rows x 8 h (4 f32x2 pairs) per thread.
// =========================================================================
#define PROJ_SMEM ((16384 + 128*132) * 4)

__global__ void __launch_bounds__(256, 1) proj1_kernel(
    const int* __restrict__ x, const float* __restrict__ embed,
    const float* __restrict__ W_ih, const float* __restrict__ b_ih)
{
    extern __shared__ float sm[];
    float* As = sm;            // [128 rows][128 e]
    float* Ws = sm + 16384;    // [128 e][132] = Wi1^T

    const int tid = threadIdx.x;
    const int rowBase = blockIdx.x * 128;

    for (int i = tid; i < 16384; i += 256) {
        int h = i >> 7, e = i & 127;
        Ws[e * 132 + h] = W_ih[i];
    }
    for (int i = tid; i < 128 * 32; i += 256) {
        int r = i >> 5, ec = i & 31;
        int token = x[rowBase + r];
        ((float4*)As)[r * 32 + ec] = ((const float4*)embed)[token * 32 + ec];
    }
    __syncthreads();

    const int tx = tid & 15, ty = tid >> 4;
    const int r0 = ty * 8, h0 = tx * 8;

    // bias as packed h-pairs
    ulonglong2 bA = *(const ulonglong2*)(b_ih + h0);
    ulonglong2 bB = *(const ulonglong2*)(b_ih + h0 + 4);
    ull bp[4] = {bA.x, bA.y, bB.x, bB.y};

    ull acc[8][4];
#pragma unroll
    for (int i = 0; i < 8; i++)
#pragma unroll
        for (int p = 0; p < 4; p++) acc[i][p] = bp[p];

#pragma unroll 4
    for (int k = 0; k < 128; k++) {
        ulonglong2 w0 = *(const ulonglong2*)(Ws + k * 132 + h0);
        ulonglong2 w1 = *(const ulonglong2*)(Ws + k * 132 + h0 + 4);
        ull wp[4] = {w0.x, w0.y, w1.x, w1.y};
        ull ap[8];
#pragma unroll
        for (int i = 0; i < 8; i++) {
            float a = As[(r0 + i) * 128 + k];
            ap[i] = pack2(a, a);
        }
#pragma unroll
        for (int i = 0; i < 8; i++)
#pragma unroll
            for (int p = 0; p < 4; p++)
                acc[i][p] = ffma2(wp[p], ap[i], acc[i][p]);
    }

#pragma unroll
    for (int i = 0; i < 8; i++) {
        ull* o = (ull*)(g_pre1 + (size_t)(rowBase + r0 + i) * 128 + h0);
        o[0] = acc[i][0]; o[1] = acc[i][1]; o[2] = acc[i][2]; o[3] = acc[i][3];
    }
}

// =========================================================================
// Kernel 2: fused 2-layer recurrent scan.
// CTA: 32 sequences, 256 threads (thread = 8 h-dims (4 f32x2) x 2 seqs).
// SMEM: 3 transposed weights [k][h] + 2 state arrays [h][34] (s-pairs).
// =========================================================================
#define HS_PITCH 34
#define SCAN_SMEM (3 * 16384 * 4 + 2 * 128 * HS_PITCH * 4)   // 231424 B

__device__ __forceinline__ void gemv2(const float* __restrict__ WT,
                                      const float* __restrict__ hs,
                                      int h0, int s0,
                                      ull acc0[4], ull acc1[4])
{
#pragma unroll 8
    for (int k = 0; k < 128; k++) {
        ulonglong2 w0 = *(const ulonglong2*)(WT + k * 128 + h0);
        ulonglong2 w1 = *(const ulonglong2*)(WT + k * 128 + h0 + 4);
        float2 hv = *(const float2*)(hs + k * HS_PITCH + s0);
        ull ha = pack2(hv.x, hv.x);
        ull hb = pack2(hv.y, hv.y);
        acc0[0] = ffma2(w0.x, ha, acc0[0]);
        acc0[1] = ffma2(w0.y, ha, acc0[1]);
        acc0[2] = ffma2(w1.x, ha, acc0[2]);
        acc0[3] = ffma2(w1.y, ha, acc0[3]);
        acc1[0] = ffma2(w0.x, hb, acc1[0]);
        acc1[1] = ffma2(w0.y, hb, acc1[1]);
        acc1[2] = ffma2(w1.x, hb, acc1[2]);
        acc1[3] = ffma2(w1.y, hb, acc1[3]);
    }
}

__global__ void __launch_bounds__(256, 1) scan_kernel(
    const float* __restrict__ W_ih, const float* __restrict__ W_hh,
    const float* __restrict__ b_ih, const float* __restrict__ b_hh)
{
    extern __shared__ float sm[];
    float* W1T = sm;             // Wh layer0 ^T  [k][h]
    float* WiT = sm + 16384;     // Wi layer1 ^T
    float* W2T = sm + 32768;     // Wh layer1 ^T
    float* h1s = sm + 49152;     // [128][HS_PITCH]
    float* h2s = h1s + 128 * HS_PITCH;

    const int tid = threadIdx.x;

    for (int i = tid; i < 16384; i += 256) {
        int h = i >> 7, k = i & 127;
        W1T[k * 128 + h] = W_hh[i];
        WiT[k * 128 + h] = W_ih[16384 + i];
        W2T[k * 128 + h] = W_hh[16384 + i];
    }
    for (int i = tid; i < 2 * 128 * HS_PITCH; i += 256) h1s[i] = 0.f;

    const int hx = tid & 15, sg = tid >> 4;
    const int h0 = hx * 8, s0 = sg * 2;
    const int seq0 = blockIdx.x * 32 + s0;   // this thread handles seq0, seq0+1

    // biases as packed h-pairs
    ull bp1[4], bp2[4];
#pragma unroll
    for (int p = 0; p < 4; p++) {
        bp1[p] = pack2(b_hh[h0 + 2*p], b_hh[h0 + 2*p + 1]);
        bp2[p] = pack2(b_ih[128 + h0 + 2*p] + b_hh[128 + h0 + 2*p],
                       b_ih[128 + h0 + 2*p + 1] + b_hh[128 + h0 + 2*p + 1]);
    }
    __syncthreads();

    const float* preA = g_pre1 + ((size_t)seq0 * SLEN) * 128 + h0;
    const float* preB = preA + (size_t)SLEN * 128;

    // prefetch t=0
    ulonglong2 cA0 = *(const ulonglong2*)(preA);
    ulonglong2 cA1 = *(const ulonglong2*)(preA + 4);
    ulonglong2 cB0 = *(const ulonglong2*)(preB);
    ulonglong2 cB1 = *(const ulonglong2*)(preB + 4);

    for (int t = 0; t < SLEN; t++) {
        // ---- Layer 1 ----
        ull a0[4] = {cA0.x, cA0.y, cA1.x, cA1.y};
        ull a1[4] = {cB0.x, cB0.y, cB1.x, cB1.y};
        if (t + 1 < SLEN) {
            const float* pA = preA + (t + 1) * 128;
            const float* pB = preB + (t + 1) * 128;
            cA0 = *(const ulonglong2*)(pA);
            cA1 = *(const ulonglong2*)(pA + 4);
            cB0 = *(const ulonglong2*)(pB);
            cB1 = *(const ulonglong2*)(pB + 4);
        }
        gemv2(W1T, h1s, h0, s0, a0, a1);
        __syncthreads();                       // reads of old h1s done
#pragma unroll
        for (int p = 0; p < 4; p++) {
            float2 u0 = unpack2(add2(a0[p], bp1[p]));
            float2 u1 = unpack2(add2(a1[p], bp1[p]));
            *(float2*)(h1s + (h0 + 2*p)     * HS_PITCH + s0) =
                make_float2(fmaxf(u0.x, 0.f), fmaxf(u1.x, 0.f));
            *(float2*)(h1s + (h0 + 2*p + 1) * HS_PITCH + s0) =
                make_float2(fmaxf(u0.y, 0.f), fmaxf(u1.y, 0.f));
        }
        __syncthreads();                       // new h1s visible

        // ---- Layer 2 ----
        ull c0[4], c1[4];
#pragma unroll
        for (int p = 0; p < 4; p++) { c0[p] = bp2[p]; c1[p] = bp2[p]; }
        gemv2(WiT, h1s, h0, s0, c0, c1);
        gemv2(W2T, h2s, h0, s0, c0, c1);
        __syncthreads();                       // reads of old h2s done
#pragma unroll
        for (int p = 0; p < 4; p++) {
            float2 u0 = unpack2(c0[p]);
            float2 u1 = unpack2(c1[p]);
            float r00 = fmaxf(u0.x, 0.f), r01 = fmaxf(u0.y, 0.f);
            float r10 = fmaxf(u1.x, 0.f), r11 = fmaxf(u1.y, 0.f);
            *(float2*)(h2s + (h0 + 2*p)     * HS_PITCH + s0) = make_float2(r00, r10);
            *(float2*)(h2s + (h0 + 2*p + 1) * HS_PITCH + s0) = make_float2(r01, r11);
            if (t == SLEN - 1) {
                g_h[(size_t)seq0 * 128 + h0 + 2*p]           = r00;
                g_h[(size_t)seq0 * 128 + h0 + 2*p + 1]       = r01;
                g_h[(size_t)(seq0 + 1) * 128 + h0 + 2*p]     = r10;
                g_h[(size_t)(seq0 + 1) * 128 + h0 + 2*p + 1] = r11;
            }
        }
        // no 4th barrier: next-step barriers cover the h2s store->read hazard
    }
}

// =========================================================================
// Kernel 3a: u[n] = w1.h[n], v[n] = w2.h[n]
// =========================================================================
__global__ void reduce1_kernel(const float* __restrict__ predW)
{
    int gwarp = (blockIdx.x * blockDim.x + threadIdx.x) >> 5;
    int lane = threadIdx.x & 31;
    if (gwarp >= NSEQ) return;
    const float* hr = g_h + (size_t)gwarp * 128;
    float su = 0.f, sv = 0.f;
#pragma unroll
    for (int i = 0; i < 4; i++) {
        int idx = lane + 32 * i;
        float hv = hr[idx];
        su += hv * predW[idx];
        sv += hv * predW[128 + idx];
    }
#pragma unroll
    for (int o = 16; o; o >>= 1) {
        su += __shfl_xor_sync(0xffffffffu, su, o);
        sv += __shfl_xor_sync(0xffffffffu, sv, o);
    }
    if (lane == 0) { g_u[gwarp] = su; g_v[gwarp] = sv; }
}

// =========================================================================
// Kernel 3b: out = u - 2v + rowsum(v) + colsum(v) + pred_b
// =========================================================================
__global__ void reduce2_kernel(const float* __restrict__ pred_b,
                               float* __restrict__ out)
{
    __shared__ float vs[NR * NC];
    __shared__ float RS[NR], CS[NC];
    const int b = blockIdx.x, tid = threadIdx.x;

    for (int i = tid; i < NR * NC; i += 256) vs[i] = g_v[b * NR * NC + i];
    __syncthreads();
    if (tid < NR) {
        float sr = 0.f;
        for (int c = 0; c < NC; c++) sr += vs[tid * NC + c];
        RS[tid] = sr;
    } else if (tid < NR + NC) {
        int c = tid - NR;
        float sc = 0.f;
        for (int r = 0; r < NR; r++) sc += vs[r * NC + c];
        CS[c] = sc;
    }
    __syncthreads();
    float pb = pred_b[0];
    for (int i = tid; i < NR * NC; i += 256) {
        int r = i >> 6, c = i & 63;
        out[b * NR * NC + i] =
            g_u[b * NR * NC + i] - 2.f * vs[i] + RS[r] + CS[c] + pb;
    }
}

// =========================================================================
extern "C" void kernel_launch(void* const* d_in, const int* in_sizes, int n_in,
                              void* d_out, int out_size)
{
    const int*   x      = (const int*)  d_in[0];
    const float* embed  = (const float*)d_in[1];
    const float* W_ih   = (const float*)d_in[2];
    const float* W_hh   = (const float*)d_in[3];
    const float* b_ih   = (const float*)d_in[4];
    const float* b_hh   = (const float*)d_in[5];
    const float* pred_W = (const float*)d_in[6];
    const float* pred_b = (const float*)d_in[7];
    float* out = (float*)d_out;

    cudaFuncSetAttribute(proj1_kernel, cudaFuncAttributeMaxDynamicSharedMemorySize, PROJ_SMEM);
    cudaFuncSetAttribute(scan_kernel,  cudaFuncAttributeMaxDynamicSharedMemorySize, SCAN_SMEM);

    proj1_kernel<<<NROWS / 128, 256, PROJ_SMEM>>>(x, embed, W_ih, b_ih);
    scan_kernel<<<NSEQ / 32, 256, SCAN_SMEM>>>(W_ih, W_hh, b_ih, b_hh);
    reduce1_kernel<<<NSEQ / 8, 256>>>(pred_W);
    reduce2_kernel<<<NB, 256>>>(pred_b, out);
}

// round 3
// speedup vs baseline: 2.5671x; 1.6142x over previous
#include <cuda_runtime.h>
#include <cuda_bf16.h>

// Problem constants
#define NB 4
#define NR 64
#define NC 64
#define NSEQ (NB*NR*NC)     // 16384
#define SLEN 32
#define HD 128
#define NROWS (NSEQ*SLEN)   // 524288

typedef unsigned long long ull;

// ---------------- device scratch (no allocation allowed) ----------------
__device__ float g_pre1[(size_t)NROWS * HD];   // 256 MB
__device__ float g_h[(size_t)NSEQ * HD];       // 8 MB
__device__ float g_u[NSEQ];
__device__ float g_v[NSEQ];

// ---------------- f32x2 helpers (sm_103a packed fp32) -------------------
__device__ __forceinline__ ull pack2(float lo, float hi) {
    ull r; asm("mov.b64 %0, {%1, %2};" : "=l"(r) : "f"(lo), "f"(hi)); return r;
}
__device__ __forceinline__ ull ffma2(ull a, ull b, ull c) {
    ull d; asm("fma.rn.f32x2 %0, %1, %2, %3;" : "=l"(d) : "l"(a), "l"(b), "l"(c)); return d;
}
__device__ __forceinline__ ull add2(ull a, ull b) {
    ull d; asm("add.rn.f32x2 %0, %1, %2;" : "=l"(d) : "l"(a), "l"(b)); return d;
}
__device__ __forceinline__ float2 unpack2(ull v) {
    float2 f; asm("mov.b64 {%0, %1}, %2;" : "=f"(f.x), "=f"(f.y) : "l"(v)); return f;
}

// =========================================================================
// Kernel 1: pre1[row][h] = embed[x[row]] @ Wi1^T + bi1   (row = n*S + t)
// 128x128 tile, 256 threads. Thread (tx,ty): rows ty*8..+8,
// h-dims {4tx..4tx+3} U {64+4tx..+3}  -> conflict-free LDS.128.
// =========================================================================
#define WS_PITCH 136
#define PROJ_SMEM ((16384 + 128*WS_PITCH) * 4)

__global__ void __launch_bounds__(256, 1) proj1_kernel(
    const int* __restrict__ x, const float* __restrict__ embed,
    const float* __restrict__ W_ih, const float* __restrict__ b_ih)
{
    extern __shared__ float sm[];
    float* As = sm;            // [128 rows][128 e]
    float* Ws = sm + 16384;    // [128 e][WS_PITCH] = Wi1^T

    const int tid = threadIdx.x;
    const int rowBase = blockIdx.x * 128;

    for (int i = tid; i < 16384; i += 256) {
        int h = i >> 7, e = i & 127;
        Ws[e * WS_PITCH + h] = W_ih[i];
    }
    for (int i = tid; i < 128 * 32; i += 256) {
        int r = i >> 5, ec = i & 31;
        int token = x[rowBase + r];
        ((float4*)As)[r * 32 + ec] = ((const float4*)embed)[token * 32 + ec];
    }
    __syncthreads();

    const int tx = tid & 15, ty = tid >> 4;
    const int r0 = ty * 8;
    const int hA = 4 * tx, hB = 64 + 4 * tx;

    // bias packed: pairs (hA,hA+1)(hA+2,hA+3)(hB,hB+1)(hB+2,hB+3)
    ull bp[4];
    bp[0] = pack2(b_ih[hA], b_ih[hA + 1]);
    bp[1] = pack2(b_ih[hA + 2], b_ih[hA + 3]);
    bp[2] = pack2(b_ih[hB], b_ih[hB + 1]);
    bp[3] = pack2(b_ih[hB + 2], b_ih[hB + 3]);

    ull acc[8][4];
#pragma unroll
    for (int i = 0; i < 8; i++)
#pragma unroll
        for (int p = 0; p < 4; p++) acc[i][p] = bp[p];

#pragma unroll 4
    for (int k = 0; k < 128; k++) {
        ulonglong2 wA = *(const ulonglong2*)(Ws + k * WS_PITCH + hA);
        ulonglong2 wB = *(const ulonglong2*)(Ws + k * WS_PITCH + hB);
        ull wp[4] = {wA.x, wA.y, wB.x, wB.y};
        ull ap[8];
#pragma unroll
        for (int i = 0; i < 8; i++) {
            float a = As[(r0 + i) * 128 + k];
            ap[i] = pack2(a, a);
        }
#pragma unroll
        for (int i = 0; i < 8; i++)
#pragma unroll
            for (int p = 0; p < 4; p++)
                acc[i][p] = ffma2(wp[p], ap[i], acc[i][p]);
    }

#pragma unroll
    for (int i = 0; i < 8; i++) {
        float* o = g_pre1 + (size_t)(rowBase + r0 + i) * 128;
        ((ull*)(o + hA))[0] = acc[i][0];
        ((ull*)(o + hA))[1] = acc[i][1];
        ((ull*)(o + hB))[0] = acc[i][2];
        ((ull*)(o + hB))[1] = acc[i][3];
    }
}

// =========================================================================
// Kernel 2: fused 2-layer recurrent scan.
// CTA: 32 sequences, 256 threads. Thread (hx,sg): 2 seqs (s0=2sg),
// h-dims {4hx..} U {64+4hx..} -> conflict-free weight LDS.128.
// =========================================================================
#define HS_PITCH 34
#define SCAN_SMEM (3 * 16384 * 4 + 2 * 128 * HS_PITCH * 4)   // 231424 B

__device__ __forceinline__ void gemv2(const float* __restrict__ WT,
                                      const float* __restrict__ hs,
                                      int hA, int hB, int s0,
                                      ull acc0[4], ull acc1[4])
{
#pragma unroll 8
    for (int k = 0; k < 128; k++) {
        ulonglong2 wA = *(const ulonglong2*)(WT + k * 128 + hA);
        ulonglong2 wB = *(const ulonglong2*)(WT + k * 128 + hB);
        float2 hv = *(const float2*)(hs + k * HS_PITCH + s0);
        ull ha = pack2(hv.x, hv.x);
        ull hb = pack2(hv.y, hv.y);
        acc0[0] = ffma2(wA.x, ha, acc0[0]);
        acc0[1] = ffma2(wA.y, ha, acc0[1]);
        acc0[2] = ffma2(wB.x, ha, acc0[2]);
        acc0[3] = ffma2(wB.y, ha, acc0[3]);
        acc1[0] = ffma2(wA.x, hb, acc1[0]);
        acc1[1] = ffma2(wA.y, hb, acc1[1]);
        acc1[2] = ffma2(wB.x, hb, acc1[2]);
        acc1[3] = ffma2(wB.y, hb, acc1[3]);
    }
}

__global__ void __launch_bounds__(256, 1) scan_kernel(
    const float* __restrict__ W_ih, const float* __restrict__ W_hh,
    const float* __restrict__ b_ih, const float* __restrict__ b_hh)
{
    extern __shared__ float sm[];
    float* W1T = sm;             // Wh layer0 ^T  [k][h]
    float* WiT = sm + 16384;     // Wi layer1 ^T
    float* W2T = sm + 32768;     // Wh layer1 ^T
    float* h1s = sm + 49152;     // [128][HS_PITCH]
    float* h2s = h1s + 128 * HS_PITCH;

    const int tid = threadIdx.x;

    for (int i = tid; i < 16384; i += 256) {
        int h = i >> 7, k = i & 127;
        W1T[k * 128 + h] = W_hh[i];
        WiT[k * 128 + h] = W_ih[16384 + i];
        W2T[k * 128 + h] = W_hh[16384 + i];
    }
    for (int i = tid; i < 2 * 128 * HS_PITCH; i += 256) h1s[i] = 0.f;

    const int hx = tid & 15, sg = tid >> 4;
    const int hA = 4 * hx, hB = 64 + 4 * hx;
    const int s0 = sg * 2;
    const int seq0 = blockIdx.x * 32 + s0;

    // biases as packed pairs (hA,hA+1)(hA+2,hA+3)(hB,..)(hB+2,..)
    ull bp1[4], bp2[4];
    {
        int d[4] = {hA, hA + 2, hB, hB + 2};
#pragma unroll
        for (int p = 0; p < 4; p++) {
            bp1[p] = pack2(b_hh[d[p]], b_hh[d[p] + 1]);
            bp2[p] = pack2(b_ih[128 + d[p]] + b_hh[128 + d[p]],
                           b_ih[128 + d[p] + 1] + b_hh[128 + d[p] + 1]);
        }
    }
    __syncthreads();

    const float* pre0 = g_pre1 + (size_t)seq0 * SLEN * 128;
    const float* pre1p = pre0 + (size_t)SLEN * 128;

    // prefetch t=0
    ulonglong2 cA0 = *(const ulonglong2*)(pre0 + hA);
    ulonglong2 cA1 = *(const ulonglong2*)(pre0 + hB);
    ulonglong2 cB0 = *(const ulonglong2*)(pre1p + hA);
    ulonglong2 cB1 = *(const ulonglong2*)(pre1p + hB);

    for (int t = 0; t < SLEN; t++) {
        // ---- Layer 1 ----
        ull a0[4] = {cA0.x, cA0.y, cA1.x, cA1.y};
        ull a1[4] = {cB0.x, cB0.y, cB1.x, cB1.y};
        if (t + 1 < SLEN) {
            const float* pA = pre0 + (t + 1) * 128;
            const float* pB = pre1p + (t + 1) * 128;
            cA0 = *(const ulonglong2*)(pA + hA);
            cA1 = *(const ulonglong2*)(pA + hB);
            cB0 = *(const ulonglong2*)(pB + hA);
            cB1 = *(const ulonglong2*)(pB + hB);
        }
        gemv2(W1T, h1s, hA, hB, s0, a0, a1);
        __syncthreads();                       // reads of old h1s done
        {
            int d[4] = {hA, hA + 2, hB, hB + 2};
#pragma unroll
            for (int p = 0; p < 4; p++) {
                float2 u0 = unpack2(add2(a0[p], bp1[p]));
                float2 u1 = unpack2(add2(a1[p], bp1[p]));
                *(float2*)(h1s + d[p] * HS_PITCH + s0) =
                    make_float2(fmaxf(u0.x, 0.f), fmaxf(u1.x, 0.f));
                *(float2*)(h1s + (d[p] + 1) * HS_PITCH + s0) =
                    make_float2(fmaxf(u0.y, 0.f), fmaxf(u1.y, 0.f));
            }
        }
        __syncthreads();                       // new h1s visible

        // ---- Layer 2 ----
        ull c0[4], c1[4];
#pragma unroll
        for (int p = 0; p < 4; p++) { c0[p] = bp2[p]; c1[p] = bp2[p]; }
        gemv2(WiT, h1s, hA, hB, s0, c0, c1);
        gemv2(W2T, h2s, hA, hB, s0, c0, c1);
        __syncthreads();                       // reads of old h2s done
        {
            int d[4] = {hA, hA + 2, hB, hB + 2};
            float r0v[8], r1v[8];
#pragma unroll
            for (int p = 0; p < 4; p++) {
                float2 u0 = unpack2(c0[p]);
                float2 u1 = unpack2(c1[p]);
                r0v[2*p]   = fmaxf(u0.x, 0.f); r0v[2*p+1] = fmaxf(u0.y, 0.f);
                r1v[2*p]   = fmaxf(u1.x, 0.f); r1v[2*p+1] = fmaxf(u1.y, 0.f);
                *(float2*)(h2s + d[p] * HS_PITCH + s0) =
                    make_float2(r0v[2*p], r1v[2*p]);
                *(float2*)(h2s + (d[p] + 1) * HS_PITCH + s0) =
                    make_float2(r0v[2*p+1], r1v[2*p+1]);
            }
            if (t == SLEN - 1) {
                float* o0 = g_h + (size_t)seq0 * 128;
                float* o1 = g_h + (size_t)(seq0 + 1) * 128;
                *(float4*)(o0 + hA) = make_float4(r0v[0], r0v[1], r0v[2], r0v[3]);
                *(float4*)(o0 + hB) = make_float4(r0v[4], r0v[5], r0v[6], r0v[7]);
                *(float4*)(o1 + hA) = make_float4(r1v[0], r1v[1], r1v[2], r1v[3]);
                *(float4*)(o1 + hB) = make_float4(r1v[4], r1v[5], r1v[6], r1v[7]);
            }
        }
        // no 4th barrier: next-step barriers cover h2s store->read hazard
    }
}

// =========================================================================
// Kernel 3a: u[n] = w1.h[n], v[n] = w2.h[n]
// =========================================================================
__global__ void reduce1_kernel(const float* __restrict__ predW)
{
    int gwarp = (blockIdx.x * blockDim.x + threadIdx.x) >> 5;
    int lane = threadIdx.x & 31;
    if (gwarp >= NSEQ) return;
    const float* hr = g_h + (size_t)gwarp * 128;
    float su = 0.f, sv = 0.f;
#pragma unroll
    for (int i = 0; i < 4; i++) {
        int idx = lane + 32 * i;
        float hv = hr[idx];
        su += hv * predW[idx];
        sv += hv * predW[128 + idx];
    }
#pragma unroll
    for (int o = 16; o; o >>= 1) {
        su += __shfl_xor_sync(0xffffffffu, su, o);
        sv += __shfl_xor_sync(0xffffffffu, sv, o);
    }
    if (lane == 0) { g_u[gwarp] = su; g_v[gwarp] = sv; }
}

// =========================================================================
// Kernel 3b: out = u - 2v + rowsum(v) + colsum(v) + pred_b
// =========================================================================
__global__ void reduce2_kernel(const float* __restrict__ pred_b,
                               float* __restrict__ out)
{
    __shared__ float vs[NR * NC];
    __shared__ float RS[NR], CS[NC];
    const int b = blockIdx.x, tid = threadIdx.x;

    for (int i = tid; i < NR * NC; i += 256) vs[i] = g_v[b * NR * NC + i];
    __syncthreads();
    if (tid < NR) {
        float sr = 0.f;
        for (int c = 0; c < NC; c++) sr += vs[tid * NC + c];
        RS[tid] = sr;
    } else if (tid < NR + NC) {
        int c = tid - NR;
        float sc = 0.f;
        for (int r = 0; r < NR; r++) sc += vs[r * NC + c];
        CS[c] = sc;
    }
    __syncthreads();
    float pb = pred_b[0];
    for (int i = tid; i < NR * NC; i += 256) {
        int r = i >> 6, c = i & 63;
        out[b * NR * NC + i] =
            g_u[b * NR * NC + i] - 2.f * vs[i] + RS[r] + CS[c] + pb;
    }
}

// =========================================================================
extern "C" void kernel_launch(void* const* d_in, const int* in_sizes, int n_in,
                              void* d_out, int out_size)
{
    const int*   x      = (const int*)  d_in[0];
    const float* embed  = (const float*)d_in[1];
    const float* W_ih   = (const float*)d_in[2];
    const float* W_hh   = (const float*)d_in[3];
    const float* b_ih   = (const float*)d_in[4];
    const float* b_hh   = (const float*)d_in[5];
    const float* pred_W = (const float*)d_in[6];
    const float* pred_b = (const float*)d_in[7];
    float* out = (float*)d_out;

    cudaFuncSetAttribute(proj1_kernel, cudaFuncAttributeMaxDynamicSharedMemorySize, PROJ_SMEM);
    cudaFuncSetAttribute(scan_kernel,  cudaFuncAttributeMaxDynamicSharedMemorySize, SCAN_SMEM);

    proj1_kernel<<<NROWS / 128, 256, PROJ_SMEM>>>(x, embed, W_ih, b_ih);
    scan_kernel<<<NSEQ / 32, 256, SCAN_SMEM>>>(W_ih, W_hh, b_ih, b_hh);
    reduce1_kernel<<<NSEQ / 8, 256>>>(pred_W);
    reduce2_kernel<<<NB, 256>>>(pred_b, out);
}

// round 5
// speedup vs baseline: 5.7981x; 2.2586x over previous
#include <cuda_runtime.h>
#include <cuda_bf16.h>
#include <cstdint>

#define NB 4
#define NR 64
#define NC 64
#define NSEQ 16384
#define SLEN 32
#define HD 128
#define NROWS (NSEQ*SLEN)
#define PKW 136                 // bf16 pitch of weight/A tiles (272B, LDSM conflict-free)
#define TILE_B (128*PKW*2)      // 34816 bytes per 128x128 bf16 tile

// ---------------- device scratch ----------------
__device__ float g_pre1[(size_t)NROWS * HD];   // [t][seq][h] 256 MB
__device__ float g_h[(size_t)NSEQ * HD];
__device__ float g_u[NSEQ];
__device__ float g_v[NSEQ];

// ================= helpers =================
__device__ __forceinline__ uint32_t smem_u32(const void* p) {
    uint32_t a;
    asm("{ .reg .u64 t; cvta.to.shared.u64 t, %1; cvt.u32.u64 %0, t; }" : "=r"(a) : "l"(p));
    return a;
}
__device__ __forceinline__ void ldsm_x4(uint32_t* r, uint32_t addr) {
    asm volatile("ldmatrix.sync.aligned.m8n8.x4.shared.b16 {%0,%1,%2,%3}, [%4];"
        : "=r"(r[0]), "=r"(r[1]), "=r"(r[2]), "=r"(r[3]) : "r"(addr));
}
__device__ __forceinline__ void mma_op(float* d, const uint32_t* a, uint32_t b0, uint32_t b1) {
    asm volatile("mma.sync.aligned.m16n8k16.row.col.f32.bf16.bf16.f32 "
        "{%0,%1,%2,%3}, {%4,%5,%6,%7}, {%8,%9}, {%0,%1,%2,%3};"
        : "+f"(d[0]), "+f"(d[1]), "+f"(d[2]), "+f"(d[3])
        : "r"(a[0]), "r"(a[1]), "r"(a[2]), "r"(a[3]), "r"(b0), "r"(b1));
}
// split (f0,f1) into bf16 hi pair + residual lo pair
__device__ __forceinline__ void split2(float f0, float f1, uint32_t& hi, uint32_t& lo) {
    __nv_bfloat16 h0 = __float2bfloat16_rn(f0), h1 = __float2bfloat16_rn(f1);
    float l0 = f0 - __bfloat162float(h0), l1 = f1 - __bfloat162float(h1);
    __nv_bfloat162 hp = __halves2bfloat162(h0, h1);
    __nv_bfloat162 lp = __halves2bfloat162(__float2bfloat16_rn(l0), __float2bfloat16_rn(l1));
    hi = *reinterpret_cast<uint32_t*>(&hp);
    lo = *reinterpret_cast<uint32_t*>(&lp);
}
// load fp32 W[128][128] -> bf16 hi/lo tiles stored [n][k] pitch PKW
__device__ void load_wtile(const float* __restrict__ W, char* hi, char* lo, int tid, int nthr) {
    for (int i = tid; i < 16384; i += nthr) {
        int n = i >> 7, k = i & 127;
        float w = W[i];
        __nv_bfloat16 h = __float2bfloat16_rn(w);
        __nv_bfloat16 l = __float2bfloat16_rn(w - __bfloat162float(h));
        *reinterpret_cast<__nv_bfloat16*>(hi + (n * PKW + k) * 2) = h;
        *reinterpret_cast<__nv_bfloat16*>(lo + (n * PKW + k) * 2) = l;
    }
}

// One pass: D[16][4] += A(fragments, 8 kchunks) x B(smem tile at wb)
__device__ __forceinline__ void mma_pass(float (*d)[4], const uint32_t* a,
                                         uint32_t wb, int lrowB, int lkofB)
{
#pragma unroll
    for (int kc = 0; kc < 8; kc++) {
#pragma unroll
        for (int half = 0; half < 2; half++) {
            uint32_t b[16];
#pragma unroll
            for (int q = 0; q < 4; q++) {
                int ntp = half * 4 + q;          // covers ntiles 2ntp, 2ntp+1
                uint32_t ad = wb + (uint32_t)(((ntp * 16 + lrowB) * PKW + kc * 16 + lkofB) * 2);
                ldsm_x4(b + 4 * q, ad);
            }
#pragma unroll
            for (int q = 0; q < 4; q++) {
                int ntp = half * 4 + q;
                mma_op(d[2 * ntp],     a + 4 * kc, b[4 * q],     b[4 * q + 1]);
                mma_op(d[2 * ntp + 1], a + 4 * kc, b[4 * q + 2], b[4 * q + 3]);
            }
        }
    }
}

// =========================================================================
// Kernel 1 (proj): pre1[t][seq][h] = embed[x[seq,t]] @ Wi1^T + (bi1+bh1)
// grid 4096 CTAs x 256 thr; CTA = 128 rows (one t, 128 seqs); 3-pass bf16.
// =========================================================================
#define P_AHI 0
#define P_ALO TILE_B
#define P_BHI (2*TILE_B)
#define P_BLO (3*TILE_B)
#define P_B1  (4*TILE_B)
#define P_TOK (4*TILE_B + 512)
#define PROJ_SMEM (4*TILE_B + 1024)

__global__ void __launch_bounds__(256, 1) proj_hmma_kernel(
    const int* __restrict__ x, const float* __restrict__ embed,
    const float* __restrict__ W_ih,
    const float* __restrict__ b_ih, const float* __restrict__ b_hh)
{
    extern __shared__ char smem[];
    const int tid = threadIdx.x;
    const int l = tid & 31, wid = tid >> 5;
    uint32_t sb = smem_u32(smem);

    const int t = blockIdx.x >> 7;
    const int seqbase = (blockIdx.x & 127) * 128;

    load_wtile(W_ih, smem + P_BHI, smem + P_BLO, tid, 256);
    if (tid < 128) ((float*)(smem + P_B1))[tid] = b_ih[tid] + b_hh[tid];
    int* toks = (int*)(smem + P_TOK);
    if (tid < 128) toks[tid] = x[(size_t)(seqbase + tid) * SLEN + t];
    __syncthreads();

    // gather + split embeddings into A hi/lo tiles [row][k] pitch PKW
    for (int i = tid; i < 128 * 32; i += 256) {
        int r = i >> 5, c = i & 31;
        float4 v = ((const float4*)embed)[(size_t)toks[r] * 32 + c];
        uint32_t h01, l01, h23, l23;
        split2(v.x, v.y, h01, l01);
        split2(v.z, v.w, h23, l23);
        uint32_t off = (uint32_t)(r * PKW + 4 * c) * 2;
        *(uint2*)(smem + P_AHI + off) = make_uint2(h01, h23);
        *(uint2*)(smem + P_ALO + off) = make_uint2(l01, l23);
    }
    __syncthreads();

    const int mrow = wid * 16;
    const int lrowB = ((l >> 4) & 1) * 8 + (l & 7);
    const int lkofB = 8 * ((l >> 3) & 1);
    const int lrowA = ((l >> 3) & 1) * 8 + (l & 7);
    const int lkofA = 8 * ((l >> 4) & 1);

    float d[16][4];
#pragma unroll
    for (int j = 0; j < 16; j++)
#pragma unroll
        for (int q = 0; q < 4; q++) d[j][q] = 0.f;

    // 3 passes: Ahi*Bhi, Ahi*Blo, Alo*Bhi
#pragma unroll
    for (int pass = 0; pass < 3; pass++) {
        uint32_t abase = sb + (pass == 2 ? P_ALO : P_AHI);
        uint32_t bbase = sb + (pass == 1 ? P_BLO : P_BHI);
#pragma unroll
        for (int kc = 0; kc < 8; kc++) {
            uint32_t a[4];
            ldsm_x4(a, abase + (uint32_t)(((mrow + lrowA) * PKW + kc * 16 + lkofA) * 2));
#pragma unroll
            for (int half = 0; half < 2; half++) {
                uint32_t b[16];
#pragma unroll
                for (int q = 0; q < 4; q++) {
                    int ntp = half * 4 + q;
                    ldsm_x4(b + 4 * q, bbase + (uint32_t)(((ntp * 16 + lrowB) * PKW + kc * 16 + lkofB) * 2));
                }
#pragma unroll
                for (int q = 0; q < 4; q++) {
                    int ntp = half * 4 + q;
                    mma_op(d[2 * ntp],     a, b[4 * q],     b[4 * q + 1]);
                    mma_op(d[2 * ntp + 1], a, b[4 * q + 2], b[4 * q + 3]);
                }
            }
        }
    }

    // epilogue: + bias, store fragments to g_pre1
    const float* b1s = (const float*)(smem + P_B1);
    const int g = l >> 2, c2 = (l & 3) * 2;
    size_t rowA = (size_t)t * NSEQ + seqbase + mrow + g;
#pragma unroll
    for (int j = 0; j < 16; j++) {
        float2 bb = *(const float2*)(b1s + 8 * j + c2);
        float* o0 = g_pre1 + rowA * HD + 8 * j + c2;
        float* o1 = o0 + 8 * HD;
        *(float2*)o0 = make_float2(d[j][0] + bb.x, d[j][1] + bb.y);
        *(float2*)o1 = make_float2(d[j][2] + bb.x, d[j][3] + bb.y);
    }
}

// =========================================================================
// Kernel 2 (scan): persistent register-fragment RNN.
// 128 CTAs x 256 thr (8 warps x 16 seqs). No syncthreads in step loop.
// =========================================================================
#define S_W1HI 0
#define S_W1LO TILE_B
#define S_WIHI (2*TILE_B)
#define S_WILO (3*TILE_B)
#define S_W2HI (4*TILE_B)
#define S_W2LO (5*TILE_B)
#define S_B2   (6*TILE_B)
#define SCAN_SMEM (6*TILE_B + 512)

__global__ void __launch_bounds__(256, 1) scan_hmma_kernel(
    const float* __restrict__ W_ih, const float* __restrict__ W_hh,
    const float* __restrict__ b_ih, const float* __restrict__ b_hh)
{
    extern __shared__ char smem[];
    const int tid = threadIdx.x;
    const int l = tid & 31, wid = tid >> 5;
    uint32_t sb = smem_u32(smem);

    load_wtile(W_hh,         smem + S_W1HI, smem + S_W1LO, tid, 256);   // Wh1
    load_wtile(W_ih + 16384, smem + S_WIHI, smem + S_WILO, tid, 256);   // Wi2
    load_wtile(W_hh + 16384, smem + S_W2HI, smem + S_W2LO, tid, 256);   // Wh2
    if (tid < 128) ((float*)(smem + S_B2))[tid] = b_ih[128 + tid] + b_hh[128 + tid];
    __syncthreads();

    const int lrowB = ((l >> 4) & 1) * 8 + (l & 7);
    const int lkofB = 8 * ((l >> 3) & 1);
    const int g = l >> 2, c2 = (l & 3) * 2;
    const int mrow = wid * 16;
    const size_t rowA = (size_t)(blockIdx.x * 128 + mrow + g);
    const float* b2s = (const float*)(smem + S_B2);

    uint32_t h1h[32], h1l[32], h2h[32], h2l[32];
#pragma unroll
    for (int i = 0; i < 32; i++) { h1h[i] = 0; h1l[i] = 0; h2h[i] = 0; h2l[i] = 0; }

    float d[16][4];

#pragma unroll 1
    for (int t = 0; t < SLEN; t++) {
        // ---- D init = pre1[t] (b1 folded by proj) ----
        const float* pre = g_pre1 + ((size_t)t * NSEQ + rowA) * HD;
#pragma unroll
        for (int j = 0; j < 16; j++) {
            float2 v0 = *(const float2*)(pre + 8 * j + c2);
            float2 v1 = *(const float2*)(pre + 8 * HD + 8 * j + c2);
            d[j][0] = v0.x; d[j][1] = v0.y; d[j][2] = v1.x; d[j][3] = v1.y;
        }

        // ---- layer 1: D += h1 x Wh1 (3-pass) ----
        mma_pass(d, h1h, sb + S_W1HI, lrowB, lkofB);
        mma_pass(d, h1h, sb + S_W1LO, lrowB, lkofB);
        mma_pass(d, h1l, sb + S_W1HI, lrowB, lkofB);

        // ---- epilogue 1: h1 = split(relu(D)) ----
#pragma unroll
        for (int kc = 0; kc < 8; kc++) {
            int j0 = 2 * kc, j1 = 2 * kc + 1;
            split2(fmaxf(d[j0][0], 0.f), fmaxf(d[j0][1], 0.f), h1h[4*kc+0], h1l[4*kc+0]);
            split2(fmaxf(d[j0][2], 0.f), fmaxf(d[j0][3], 0.f), h1h[4*kc+1], h1l[4*kc+1]);
            split2(fmaxf(d[j1][0], 0.f), fmaxf(d[j1][1], 0.f), h1h[4*kc+2], h1l[4*kc+2]);
            split2(fmaxf(d[j1][2], 0.f), fmaxf(d[j1][3], 0.f), h1h[4*kc+3], h1l[4*kc+3]);
        }

        // ---- layer 2: D = h1 x Wi2 + h2 x Wh2 (3-pass each) ----
#pragma unroll
        for (int j = 0; j < 16; j++)
#pragma unroll
            for (int q = 0; q < 4; q++) d[j][q] = 0.f;
        mma_pass(d, h1h, sb + S_WIHI, lrowB, lkofB);
        mma_pass(d, h1h, sb + S_WILO, lrowB, lkofB);
        mma_pass(d, h1l, sb + S_WIHI, lrowB, lkofB);
        mma_pass(d, h2h, sb + S_W2HI, lrowB, lkofB);
        mma_pass(d, h2h, sb + S_W2LO, lrowB, lkofB);
        mma_pass(d, h2l, sb + S_W2HI, lrowB, lkofB);

        // ---- epilogue 2: h2 = split(relu(D + b2)); store g_h at last t ----
#pragma unroll
        for (int kc = 0; kc < 8; kc++) {
            int j0 = 2 * kc, j1 = 2 * kc + 1;
            float2 bb0 = *(const float2*)(b2s + 8 * j0 + c2);
            float2 bb1 = *(const float2*)(b2s + 8 * j1 + c2);
            float f00 = fmaxf(d[j0][0] + bb0.x, 0.f), f01 = fmaxf(d[j0][1] + bb0.y, 0.f);
            float f02 = fmaxf(d[j0][2] + bb0.x, 0.f), f03 = fmaxf(d[j0][3] + bb0.y, 0.f);
            float f10 = fmaxf(d[j1][0] + bb1.x, 0.f), f11 = fmaxf(d[j1][1] + bb1.y, 0.f);
            float f12 = fmaxf(d[j1][2] + bb1.x, 0.f), f13 = fmaxf(d[j1][3] + bb1.y, 0.f);
            split2(f00, f01, h2h[4*kc+0], h2l[4*kc+0]);
            split2(f02, f03, h2h[4*kc+1], h2l[4*kc+1]);
            split2(f10, f11, h2h[4*kc+2], h2l[4*kc+2]);
            split2(f12, f13, h2h[4*kc+3], h2l[4*kc+3]);
            if (t == SLEN - 1) {
                float* o0 = g_h + rowA * HD + 8 * j0 + c2;
                float* o1 = o0 + 8 * HD;
                *(float2*)o0 = make_float2(f00, f01);
                *(float2*)o1 = make_float2(f02, f03);
                *(float2*)(o0 + 8) = make_float2(f10, f11);
                *(float2*)(o1 + 8) = make_float2(f12, f13);
            }
        }
    }
}

// =========================================================================
// Kernel 3a: u[n] = w1.h[n], v[n] = w2.h[n]
// =========================================================================
__global__ void reduce1_kernel(const float* __restrict__ predW)
{
    int gwarp = (blockIdx.x * blockDim.x + threadIdx.x) >> 5;
    int lane = threadIdx.x & 31;
    if (gwarp >= NSEQ) return;
    const float* hr = g_h + (size_t)gwarp * 128;
    float su = 0.f, sv = 0.f;
#pragma unroll
    for (int i = 0; i < 4; i++) {
        int idx = lane + 32 * i;
        float hv = hr[idx];
        su += hv * predW[idx];
        sv += hv * predW[128 + idx];
    }
#pragma unroll
    for (int o = 16; o; o >>= 1) {
        su += __shfl_xor_sync(0xffffffffu, su, o);
        sv += __shfl_xor_sync(0xffffffffu, sv, o);
    }
    if (lane == 0) { g_u[gwarp] = su; g_v[gwarp] = sv; }
}

// =========================================================================
// Kernel 3b: out = u - 2v + rowsum(v) + colsum(v) + pred_b
// =========================================================================
__global__ void reduce2_kernel(const float* __restrict__ pred_b,
                               float* __restrict__ out)
{
    __shared__ float vs[NR * NC];
    __shared__ float RS[NR], CS[NC];
    const int b = blockIdx.x, tid = threadIdx.x;

    for (int i = tid; i < NR * NC; i += 256) vs[i] = g_v[b * NR * NC + i];
    __syncthreads();
    if (tid < NR) {
        float sr = 0.f;
        for (int c = 0; c < NC; c++) sr += vs[tid * NC + c];
        RS[tid] = sr;
    } else if (tid < NR + NC) {
        int c = tid - NR;
        float sc = 0.f;
        for (int r = 0; r < NR; r++) sc += vs[r * NC + c];
        CS[c] = sc;
    }
    __syncthreads();
    float pb = pred_b[0];
    for (int i = tid; i < NR * NC; i += 256) {
        int r = i >> 6, c = i & 63;
        out[b * NR * NC + i] =
            g_u[b * NR * NC + i] - 2.f * vs[i] + RS[r] + CS[c] + pb;
    }
}

// =========================================================================
extern "C" void kernel_launch(void* const* d_in, const int* in_sizes, int n_in,
                              void* d_out, int out_size)
{
    const int*   x      = (const int*)  d_in[0];
    const float* embed  = (const float*)d_in[1];
    const float* W_ih   = (const float*)d_in[2];
    const float* W_hh   = (const float*)d_in[3];
    const float* b_ih   = (const float*)d_in[4];
    const float* b_hh   = (const float*)d_in[5];
    const float* pred_W = (const float*)d_in[6];
    const float* pred_b = (const float*)d_in[7];
    float* out = (float*)d_out;

    cudaFuncSetAttribute(proj_hmma_kernel, cudaFuncAttributeMaxDynamicSharedMemorySize, PROJ_SMEM);
    cudaFuncSetAttribute(scan_hmma_kernel, cudaFuncAttributeMaxDynamicSharedMemorySize, SCAN_SMEM);

    proj_hmma_kernel<<<4096, 256, PROJ_SMEM>>>(x, embed, W_ih, b_ih, b_hh);
    scan_hmma_kernel<<<128, 256, SCAN_SMEM>>>(W_ih, W_hh, b_ih, b_hh);
    reduce1_kernel<<<NSEQ / 8, 256>>>(pred_W);
    reduce2_kernel<<<NB, 256>>>(pred_b, out);
}

// round 6
// speedup vs baseline: 8.8264x; 1.5223x over previous
#include <cuda_runtime.h>
#include <cuda_bf16.h>
#include <cstdint>

#define NB 4
#define NR 64
#define NC 64
#define NSEQ 16384
#define SLEN 32
#define HD 128
#define NROWS (NSEQ*SLEN)
#define PKW 136                 // bf16 pitch of weight/A tiles (272B, LDSM conflict-free)
#define TILE_B (128*PKW*2)      // 34816 bytes per 128x128 bf16 tile

// ---------------- device scratch ----------------
__device__ float g_pre1[(size_t)NROWS * HD];   // [t][seq][h] 256 MB
__device__ float g_h[(size_t)NSEQ * HD];
__device__ float g_u[NSEQ];
__device__ float g_v[NSEQ];

// ================= helpers =================
__device__ __forceinline__ uint32_t smem_u32(const void* p) {
    uint32_t a;
    asm("{ .reg .u64 t; cvta.to.shared.u64 t, %1; cvt.u32.u64 %0, t; }" : "=r"(a) : "l"(p));
    return a;
}
__device__ __forceinline__ void ldsm_x4(uint32_t* r, uint32_t addr) {
    asm volatile("ldmatrix.sync.aligned.m8n8.x4.shared.b16 {%0,%1,%2,%3}, [%4];"
        : "=r"(r[0]), "=r"(r[1]), "=r"(r[2]), "=r"(r[3]) : "r"(addr));
}
__device__ __forceinline__ void mma_op(float* d, const uint32_t* a, uint32_t b0, uint32_t b1) {
    asm volatile("mma.sync.aligned.m16n8k16.row.col.f32.bf16.bf16.f32 "
        "{%0,%1,%2,%3}, {%4,%5,%6,%7}, {%8,%9}, {%0,%1,%2,%3};"
        : "+f"(d[0]), "+f"(d[1]), "+f"(d[2]), "+f"(d[3])
        : "r"(a[0]), "r"(a[1]), "r"(a[2]), "r"(a[3]), "r"(b0), "r"(b1));
}
// split (f0,f1) into bf16 hi pair + residual lo pair
__device__ __forceinline__ void split2(float f0, float f1, uint32_t& hi, uint32_t& lo) {
    __nv_bfloat16 h0 = __float2bfloat16_rn(f0), h1 = __float2bfloat16_rn(f1);
    float l0 = f0 - __bfloat162float(h0), l1 = f1 - __bfloat162float(h1);
    __nv_bfloat162 hp = __halves2bfloat162(h0, h1);
    __nv_bfloat162 lp = __halves2bfloat162(__float2bfloat16_rn(l0), __float2bfloat16_rn(l1));
    hi = *reinterpret_cast<uint32_t*>(&hp);
    lo = *reinterpret_cast<uint32_t*>(&lp);
}
// load fp32 W[128][128] -> bf16 hi/lo tiles stored [n][k] pitch PKW
__device__ void load_wtile(const float* __restrict__ W, char* hi, char* lo, int tid, int nthr) {
    for (int i = tid; i < 16384; i += nthr) {
        int n = i >> 7, k = i & 127;
        float w = W[i];
        __nv_bfloat16 h = __float2bfloat16_rn(w);
        __nv_bfloat16 l = __float2bfloat16_rn(w - __bfloat162float(h));
        *reinterpret_cast<__nv_bfloat16*>(hi + (n * PKW + k) * 2) = h;
        *reinterpret_cast<__nv_bfloat16*>(lo + (n * PKW + k) * 2) = l;
    }
}

// Single-A pass: D += A x B(smem tile at wb)
__device__ __forceinline__ void mma_pass1(float (*d)[4], const uint32_t* a,
                                          uint32_t wb, int lrowB, int lkofB)
{
#pragma unroll
    for (int kc = 0; kc < 8; kc++) {
#pragma unroll
        for (int half = 0; half < 2; half++) {
            uint32_t b[16];
#pragma unroll
            for (int q = 0; q < 4; q++) {
                int ntp = half * 4 + q;
                ldsm_x4(b + 4 * q, wb + (uint32_t)(((ntp * 16 + lrowB) * PKW + kc * 16 + lkofB) * 2));
            }
#pragma unroll
            for (int q = 0; q < 4; q++) {
                int ntp = half * 4 + q;
                mma_op(d[2 * ntp],     a + 4 * kc, b[4 * q],     b[4 * q + 1]);
                mma_op(d[2 * ntp + 1], a + 4 * kc, b[4 * q + 2], b[4 * q + 3]);
            }
        }
    }
}

// Dual-A pass: D += (A0 + A1) x B — B fragments loaded ONCE (crossbar saver)
__device__ __forceinline__ void mma_pass2(float (*d)[4], const uint32_t* a0, const uint32_t* a1,
                                          uint32_t wb, int lrowB, int lkofB)
{
#pragma unroll
    for (int kc = 0; kc < 8; kc++) {
#pragma unroll
        for (int half = 0; half < 2; half++) {
            uint32_t b[16];
#pragma unroll
            for (int q = 0; q < 4; q++) {
                int ntp = half * 4 + q;
                ldsm_x4(b + 4 * q, wb + (uint32_t)(((ntp * 16 + lrowB) * PKW + kc * 16 + lkofB) * 2));
            }
#pragma unroll
            for (int q = 0; q < 4; q++) {
                int ntp = half * 4 + q;
                mma_op(d[2 * ntp],     a0 + 4 * kc, b[4 * q],     b[4 * q + 1]);
                mma_op(d[2 * ntp + 1], a0 + 4 * kc, b[4 * q + 2], b[4 * q + 3]);
                mma_op(d[2 * ntp],     a1 + 4 * kc, b[4 * q],     b[4 * q + 1]);
                mma_op(d[2 * ntp + 1], a1 + 4 * kc, b[4 * q + 2], b[4 * q + 3]);
            }
        }
    }
}

// =========================================================================
// Kernel 1 (proj): pre1[t][seq][h] = embed[x[seq,t]] @ Wi1^T + (bi1+bh1)
// grid 512 CTAs x 256 thr; 8 tiles per CTA (weight conversion amortized).
// =========================================================================
#define P_AHI 0
#define P_ALO TILE_B
#define P_BHI (2*TILE_B)
#define P_BLO (3*TILE_B)
#define P_B1  (4*TILE_B)
#define P_TOK (4*TILE_B + 512)
#define PROJ_SMEM (4*TILE_B + 1024)

__global__ void __launch_bounds__(256, 1) proj_hmma_kernel(
    const int* __restrict__ x, const float* __restrict__ embed,
    const float* __restrict__ W_ih,
    const float* __restrict__ b_ih, const float* __restrict__ b_hh)
{
    extern __shared__ char smem[];
    const int tid = threadIdx.x;
    const int l = tid & 31, wid = tid >> 5;
    uint32_t sb = smem_u32(smem);

    load_wtile(W_ih, smem + P_BHI, smem + P_BLO, tid, 256);
    if (tid < 128) ((float*)(smem + P_B1))[tid] = b_ih[tid] + b_hh[tid];
    int* toks = (int*)(smem + P_TOK);
    const float* b1s = (const float*)(smem + P_B1);

    const int mrow = wid * 16;
    const int lrowB = ((l >> 4) & 1) * 8 + (l & 7);
    const int lkofB = 8 * ((l >> 3) & 1);
    const int lrowA = ((l >> 3) & 1) * 8 + (l & 7);
    const int lkofA = 8 * ((l >> 4) & 1);
    const int g = l >> 2, c2 = (l & 3) * 2;

    for (int it = 0; it < 8; it++) {
        const int tile = blockIdx.x * 8 + it;
        const int t = tile >> 7;
        const int seqbase = (tile & 127) * 128;

        __syncthreads();   // weights ready (it=0) / A+toks free (it>0)
        if (tid < 128) toks[tid] = x[(size_t)(seqbase + tid) * SLEN + t];
        __syncthreads();

        // gather + split embeddings into A hi/lo tiles [row][k] pitch PKW
        for (int i = tid; i < 128 * 32; i += 256) {
            int r = i >> 5, c = i & 31;
            float4 v = ((const float4*)embed)[(size_t)toks[r] * 32 + c];
            uint32_t h01, l01, h23, l23;
            split2(v.x, v.y, h01, l01);
            split2(v.z, v.w, h23, l23);
            uint32_t off = (uint32_t)(r * PKW + 4 * c) * 2;
            *(uint2*)(smem + P_AHI + off) = make_uint2(h01, h23);
            *(uint2*)(smem + P_ALO + off) = make_uint2(l01, l23);
        }
        __syncthreads();

        float d[16][4];
#pragma unroll
        for (int j = 0; j < 16; j++)
#pragma unroll
            for (int q = 0; q < 4; q++) d[j][q] = 0.f;

        // fused pass: B=Bhi, A = Ahi + Alo (B loaded once)
#pragma unroll
        for (int kc = 0; kc < 8; kc++) {
            uint32_t ah[4], al[4];
            uint32_t aoff = (uint32_t)(((mrow + lrowA) * PKW + kc * 16 + lkofA) * 2);
            ldsm_x4(ah, sb + P_AHI + aoff);
            ldsm_x4(al, sb + P_ALO + aoff);
#pragma unroll
            for (int half = 0; half < 2; half++) {
                uint32_t b[16];
#pragma unroll
                for (int q = 0; q < 4; q++) {
                    int ntp = half * 4 + q;
                    ldsm_x4(b + 4 * q, sb + P_BHI + (uint32_t)(((ntp * 16 + lrowB) * PKW + kc * 16 + lkofB) * 2));
                }
#pragma unroll
                for (int q = 0; q < 4; q++) {
                    int ntp = half * 4 + q;
                    mma_op(d[2 * ntp],     ah, b[4 * q],     b[4 * q + 1]);
                    mma_op(d[2 * ntp + 1], ah, b[4 * q + 2], b[4 * q + 3]);
                    mma_op(d[2 * ntp],     al, b[4 * q],     b[4 * q + 1]);
                    mma_op(d[2 * ntp + 1], al, b[4 * q + 2], b[4 * q + 3]);
                }
            }
        }
        // single pass: B=Blo, A=Ahi
#pragma unroll
        for (int kc = 0; kc < 8; kc++) {
            uint32_t ah[4];
            ldsm_x4(ah, sb + P_AHI + (uint32_t)(((mrow + lrowA) * PKW + kc * 16 + lkofA) * 2));
#pragma unroll
            for (int half = 0; half < 2; half++) {
                uint32_t b[16];
#pragma unroll
                for (int q = 0; q < 4; q++) {
                    int ntp = half * 4 + q;
                    ldsm_x4(b + 4 * q, sb + P_BLO + (uint32_t)(((ntp * 16 + lrowB) * PKW + kc * 16 + lkofB) * 2));
                }
#pragma unroll
                for (int q = 0; q < 4; q++) {
                    int ntp = half * 4 + q;
                    mma_op(d[2 * ntp],     ah, b[4 * q],     b[4 * q + 1]);
                    mma_op(d[2 * ntp + 1], ah, b[4 * q + 2], b[4 * q + 3]);
                }
            }
        }

        // epilogue: + bias, store fragments to g_pre1
        size_t rowA = (size_t)t * NSEQ + seqbase + mrow + g;
#pragma unroll
        for (int j = 0; j < 16; j++) {
            float2 bb = *(const float2*)(b1s + 8 * j + c2);
            float* o0 = g_pre1 + rowA * HD + 8 * j + c2;
            float* o1 = o0 + 8 * HD;
            *(float2*)o0 = make_float2(d[j][0] + bb.x, d[j][1] + bb.y);
            *(float2*)o1 = make_float2(d[j][2] + bb.x, d[j][3] + bb.y);
        }
    }
}

// =========================================================================
// Kernel 2 (scan): persistent register-fragment RNN.
// 128 CTAs x 256 thr (8 warps x 16 seqs). No syncthreads in step loop.
// =========================================================================
#define S_W1HI 0
#define S_W1LO TILE_B
#define S_WIHI (2*TILE_B)
#define S_WILO (3*TILE_B)
#define S_W2HI (4*TILE_B)
#define S_W2LO (5*TILE_B)
#define S_B2   (6*TILE_B)
#define SCAN_SMEM (6*TILE_B + 512)

__global__ void __launch_bounds__(256, 1) scan_hmma_kernel(
    const float* __restrict__ W_ih, const float* __restrict__ W_hh,
    const float* __restrict__ b_ih, const float* __restrict__ b_hh)
{
    extern __shared__ char smem[];
    const int tid = threadIdx.x;
    const int l = tid & 31, wid = tid >> 5;
    uint32_t sb = smem_u32(smem);

    load_wtile(W_hh,         smem + S_W1HI, smem + S_W1LO, tid, 256);   // Wh1
    load_wtile(W_ih + 16384, smem + S_WIHI, smem + S_WILO, tid, 256);   // Wi2
    load_wtile(W_hh + 16384, smem + S_W2HI, smem + S_W2LO, tid, 256);   // Wh2
    if (tid < 128) ((float*)(smem + S_B2))[tid] = b_ih[128 + tid] + b_hh[128 + tid];
    __syncthreads();

    const int lrowB = ((l >> 4) & 1) * 8 + (l & 7);
    const int lkofB = 8 * ((l >> 3) & 1);
    const int g = l >> 2, c2 = (l & 3) * 2;
    const int mrow = wid * 16;
    const size_t rowA = (size_t)(blockIdx.x * 128 + mrow + g);
    const float* b2s = (const float*)(smem + S_B2);

    uint32_t h1h[32], h1l[32], h2h[32], h2l[32];
#pragma unroll
    for (int i = 0; i < 32; i++) { h1h[i] = 0; h1l[i] = 0; h2h[i] = 0; h2l[i] = 0; }

    float d[16][4];

#pragma unroll 1
    for (int t = 0; t < SLEN; t++) {
        // ---- D init = pre1[t] (b1 folded by proj) ----
        const float* pre = g_pre1 + ((size_t)t * NSEQ + rowA) * HD;
#pragma unroll
        for (int j = 0; j < 16; j++) {
            float2 v0 = *(const float2*)(pre + 8 * j + c2);
            float2 v1 = *(const float2*)(pre + 8 * HD + 8 * j + c2);
            d[j][0] = v0.x; d[j][1] = v0.y; d[j][2] = v1.x; d[j][3] = v1.y;
        }

        // ---- layer 1: D += h1 x Wh1 (3-mult, B-shared) ----
        mma_pass2(d, h1h, h1l, sb + S_W1HI, lrowB, lkofB);
        mma_pass1(d, h1h,      sb + S_W1LO, lrowB, lkofB);

        // ---- epilogue 1: h1 = split(relu(D)) ----
#pragma unroll
        for (int kc = 0; kc < 8; kc++) {
            int j0 = 2 * kc, j1 = 2 * kc + 1;
            split2(fmaxf(d[j0][0], 0.f), fmaxf(d[j0][1], 0.f), h1h[4*kc+0], h1l[4*kc+0]);
            split2(fmaxf(d[j0][2], 0.f), fmaxf(d[j0][3], 0.f), h1h[4*kc+1], h1l[4*kc+1]);
            split2(fmaxf(d[j1][0], 0.f), fmaxf(d[j1][1], 0.f), h1h[4*kc+2], h1l[4*kc+2]);
            split2(fmaxf(d[j1][2], 0.f), fmaxf(d[j1][3], 0.f), h1h[4*kc+3], h1l[4*kc+3]);
        }

        // ---- layer 2: D = h1 x Wi2 + h2 x Wh2 (3-mult each, B-shared) ----
#pragma unroll
        for (int j = 0; j < 16; j++)
#pragma unroll
            for (int q = 0; q < 4; q++) d[j][q] = 0.f;
        mma_pass2(d, h1h, h1l, sb + S_WIHI, lrowB, lkofB);
        mma_pass1(d, h1h,      sb + S_WILO, lrowB, lkofB);
        mma_pass2(d, h2h, h2l, sb + S_W2HI, lrowB, lkofB);
        mma_pass1(d, h2h,      sb + S_W2LO, lrowB, lkofB);

        // ---- epilogue 2: h2 = split(relu(D + b2)); store g_h at last t ----
#pragma unroll
        for (int kc = 0; kc < 8; kc++) {
            int j0 = 2 * kc, j1 = 2 * kc + 1;
            float2 bb0 = *(const float2*)(b2s + 8 * j0 + c2);
            float2 bb1 = *(const float2*)(b2s + 8 * j1 + c2);
            float f00 = fmaxf(d[j0][0] + bb0.x, 0.f), f01 = fmaxf(d[j0][1] + bb0.y, 0.f);
            float f02 = fmaxf(d[j0][2] + bb0.x, 0.f), f03 = fmaxf(d[j0][3] + bb0.y, 0.f);
            float f10 = fmaxf(d[j1][0] + bb1.x, 0.f), f11 = fmaxf(d[j1][1] + bb1.y, 0.f);
            float f12 = fmaxf(d[j1][2] + bb1.x, 0.f), f13 = fmaxf(d[j1][3] + bb1.y, 0.f);
            split2(f00, f01, h2h[4*kc+0], h2l[4*kc+0]);
            split2(f02, f03, h2h[4*kc+1], h2l[4*kc+1]);
            split2(f10, f11, h2h[4*kc+2], h2l[4*kc+2]);
            split2(f12, f13, h2h[4*kc+3], h2l[4*kc+3]);
            if (t == SLEN - 1) {
                float* o0 = g_h + rowA * HD + 8 * j0 + c2;
                float* o1 = o0 + 8 * HD;
                *(float2*)o0 = make_float2(f00, f01);
                *(float2*)o1 = make_float2(f02, f03);
                *(float2*)(o0 + 8) = make_float2(f10, f11);
                *(float2*)(o1 + 8) = make_float2(f12, f13);
            }
        }
    }
}

// =========================================================================
// Kernel 3a: u[n] = w1.h[n], v[n] = w2.h[n]
// =========================================================================
__global__ void reduce1_kernel(const float* __restrict__ predW)
{
    int gwarp = (blockIdx.x * blockDim.x + threadIdx.x) >> 5;
    int lane = threadIdx.x & 31;
    if (gwarp >= NSEQ) return;
    const float* hr = g_h + (size_t)gwarp * 128;
    float su = 0.f, sv = 0.f;
#pragma unroll
    for (int i = 0; i < 4; i++) {
        int idx = lane + 32 * i;
        float hv = hr[idx];
        su += hv * predW[idx];
        sv += hv * predW[128 + idx];
    }
#pragma unroll
    for (int o = 16; o; o >>= 1) {
        su += __shfl_xor_sync(0xffffffffu, su, o);
        sv += __shfl_xor_sync(0xffffffffu, sv, o);
    }
    if (lane == 0) { g_u[gwarp] = su; g_v[gwarp] = sv; }
}

// =========================================================================
// Kernel 3b: out = u - 2v + rowsum(v) + colsum(v) + pred_b
// =========================================================================
__global__ void reduce2_kernel(const float* __restrict__ pred_b,
                               float* __restrict__ out)
{
    __shared__ float vs[NR * NC];
    __shared__ float RS[NR], CS[NC];
    const int b = blockIdx.x, tid = threadIdx.x;

    for (int i = tid; i < NR * NC; i += 256) vs[i] = g_v[b * NR * NC + i];
    __syncthreads();
    if (tid < NR) {
        float sr = 0.f;
        for (int c = 0; c < NC; c++) sr += vs[tid * NC + c];
        RS[tid] = sr;
    } else if (tid < NR + NC) {
        int c = tid - NR;
        float sc = 0.f;
        for (int r = 0; r < NR; r++) sc += vs[r * NC + c];
        CS[c] = sc;
    }
    __syncthreads();
    float pb = pred_b[0];
    for (int i = tid; i < NR * NC; i += 256) {
        int r = i >> 6, c = i & 63;
        out[b * NR * NC + i] =
            g_u[b * NR * NC + i] - 2.f * vs[i] + RS[r] + CS[c] + pb;
    }
}

// =========================================================================
extern "C" void kernel_launch(void* const* d_in, const int* in_sizes, int n_in,
                              void* d_out, int out_size)
{
    const int*   x      = (const int*)  d_in[0];
    const float* embed  = (const float*)d_in[1];
    const float* W_ih   = (const float*)d_in[2];
    const float* W_hh   = (const float*)d_in[3];
    const float* b_ih   = (const float*)d_in[4];
    const float* b_hh   = (const float*)d_in[5];
    const float* pred_W = (const float*)d_in[6];
    const float* pred_b = (const float*)d_in[7];
    float* out = (float*)d_out;

    cudaFuncSetAttribute(proj_hmma_kernel, cudaFuncAttributeMaxDynamicSharedMemorySize, PROJ_SMEM);
    cudaFuncSetAttribute(scan_hmma_kernel, cudaFuncAttributeMaxDynamicSharedMemorySize, SCAN_SMEM);

    proj_hmma_kernel<<<512, 256, PROJ_SMEM>>>(x, embed, W_ih, b_ih, b_hh);
    scan_hmma_kernel<<<128, 256, SCAN_SMEM>>>(W_ih, W_hh, b_ih, b_hh);
    reduce1_kernel<<<NSEQ / 8, 256>>>(pred_W);
    reduce2_kernel<<<NB, 256>>>(pred_b, out);
}

// round 7
// speedup vs baseline: 16.8872x; 1.9132x over previous
#include <cuda_runtime.h>
#include <cuda_bf16.h>
#include <cstdint>

#define NB 4
#define NR 64
#define NC 64
#define NSEQ 16384
#define SLEN 32
#define HD 128
#define NV 30000
#define NVPAD 30080             // 235 * 128
#define PKW 136                 // bf16 pitch of weight/A tiles (272B, LDSM conflict-free)
#define TILE_B (128*PKW*2)      // 34816 bytes per 128x128 bf16 tile

// ---------------- device scratch ----------------
__device__ float g_PE[(size_t)NVPAD * HD];     // 15.4 MB: embed @ Wi1^T + b1 (L2-resident)
__device__ float g_h[(size_t)NSEQ * HD];
__device__ float g_u[NSEQ];
__device__ float g_v[NSEQ];

// ================= helpers =================
__device__ __forceinline__ uint32_t smem_u32(const void* p) {
    uint32_t a;
    asm("{ .reg .u64 t; cvta.to.shared.u64 t, %1; cvt.u32.u64 %0, t; }" : "=r"(a) : "l"(p));
    return a;
}
__device__ __forceinline__ void ldsm_x4(uint32_t* r, uint32_t addr) {
    asm volatile("ldmatrix.sync.aligned.m8n8.x4.shared.b16 {%0,%1,%2,%3}, [%4];"
        : "=r"(r[0]), "=r"(r[1]), "=r"(r[2]), "=r"(r[3]) : "r"(addr));
}
__device__ __forceinline__ void mma_op(float* d, const uint32_t* a, uint32_t b0, uint32_t b1) {
    asm volatile("mma.sync.aligned.m16n8k16.row.col.f32.bf16.bf16.f32 "
        "{%0,%1,%2,%3}, {%4,%5,%6,%7}, {%8,%9}, {%0,%1,%2,%3};"
        : "+f"(d[0]), "+f"(d[1]), "+f"(d[2]), "+f"(d[3])
        : "r"(a[0]), "r"(a[1]), "r"(a[2]), "r"(a[3]), "r"(b0), "r"(b1));
}
// split (f0,f1) into bf16 hi pair + residual lo pair
__device__ __forceinline__ void split2(float f0, float f1, uint32_t& hi, uint32_t& lo) {
    __nv_bfloat16 h0 = __float2bfloat16_rn(f0), h1 = __float2bfloat16_rn(f1);
    float l0 = f0 - __bfloat162float(h0), l1 = f1 - __bfloat162float(h1);
    __nv_bfloat162 hp = __halves2bfloat162(h0, h1);
    __nv_bfloat162 lp = __halves2bfloat162(__float2bfloat16_rn(l0), __float2bfloat16_rn(l1));
    hi = *reinterpret_cast<uint32_t*>(&hp);
    lo = *reinterpret_cast<uint32_t*>(&lp);
}
// load fp32 W[128][128] -> bf16 hi/lo tiles stored [n][k] pitch PKW
__device__ void load_wtile(const float* __restrict__ W, char* hi, char* lo, int tid, int nthr) {
    for (int i = tid; i < 16384; i += nthr) {
        int n = i >> 7, k = i & 127;
        float w = W[i];
        __nv_bfloat16 h = __float2bfloat16_rn(w);
        __nv_bfloat16 l = __float2bfloat16_rn(w - __bfloat162float(h));
        *reinterpret_cast<__nv_bfloat16*>(hi + (n * PKW + k) * 2) = h;
        *reinterpret_cast<__nv_bfloat16*>(lo + (n * PKW + k) * 2) = l;
    }
}

// Single-A pass: D += A x B(smem tile at wb)
__device__ __forceinline__ void mma_pass1(float (*d)[4], const uint32_t* a,
                                          uint32_t wb, int lrowB, int lkofB)
{
#pragma unroll
    for (int kc = 0; kc < 8; kc++) {
#pragma unroll
        for (int half = 0; half < 2; half++) {
            uint32_t b[16];
#pragma unroll
            for (int q = 0; q < 4; q++) {
                int ntp = half * 4 + q;
                ldsm_x4(b + 4 * q, wb + (uint32_t)(((ntp * 16 + lrowB) * PKW + kc * 16 + lkofB) * 2));
            }
#pragma unroll
            for (int q = 0; q < 4; q++) {
                int ntp = half * 4 + q;
                mma_op(d[2 * ntp],     a + 4 * kc, b[4 * q],     b[4 * q + 1]);
                mma_op(d[2 * ntp + 1], a + 4 * kc, b[4 * q + 2], b[4 * q + 3]);
            }
        }
    }
}

// Dual-A pass: D += (A0 + A1) x B — B fragments loaded ONCE
__device__ __forceinline__ void mma_pass2(float (*d)[4], const uint32_t* a0, const uint32_t* a1,
                                          uint32_t wb, int lrowB, int lkofB)
{
#pragma unroll
    for (int kc = 0; kc < 8; kc++) {
#pragma unroll
        for (int half = 0; half < 2; half++) {
            uint32_t b[16];
#pragma unroll
            for (int q = 0; q < 4; q++) {
                int ntp = half * 4 + q;
                ldsm_x4(b + 4 * q, wb + (uint32_t)(((ntp * 16 + lrowB) * PKW + kc * 16 + lkofB) * 2));
            }
#pragma unroll
            for (int q = 0; q < 4; q++) {
                int ntp = half * 4 + q;
                mma_op(d[2 * ntp],     a0 + 4 * kc, b[4 * q],     b[4 * q + 1]);
                mma_op(d[2 * ntp + 1], a0 + 4 * kc, b[4 * q + 2], b[4 * q + 3]);
                mma_op(d[2 * ntp],     a1 + 4 * kc, b[4 * q],     b[4 * q + 1]);
                mma_op(d[2 * ntp + 1], a1 + 4 * kc, b[4 * q + 2], b[4 * q + 3]);
            }
        }
    }
}

// =========================================================================
// Kernel 1 (PE): PE[v][h] = embed[v] @ Wi1^T + (bi1+bh1), v = 0..NV-1
// 235 CTAs x 256 thr, one 128-vocab-row tile each, 3-mult compensated.
// =========================================================================
#define P_AHI 0
#define P_ALO TILE_B
#define P_BHI (2*TILE_B)
#define P_BLO (3*TILE_B)
#define P_B1  (4*TILE_B)
#define PROJ_SMEM (4*TILE_B + 1024)

__global__ void __launch_bounds__(256, 1) pe_hmma_kernel(
    const float* __restrict__ embed, const float* __restrict__ W_ih,
    const float* __restrict__ b_ih, const float* __restrict__ b_hh)
{
    extern __shared__ char smem[];
    const int tid = threadIdx.x;
    const int l = tid & 31, wid = tid >> 5;
    uint32_t sb = smem_u32(smem);

    const int vbase = blockIdx.x * 128;

    load_wtile(W_ih, smem + P_BHI, smem + P_BLO, tid, 256);
    if (tid < 128) ((float*)(smem + P_B1))[tid] = b_ih[tid] + b_hh[tid];
    const float* b1s = (const float*)(smem + P_B1);

    // A tile = 128 consecutive vocab embedding rows (guarded)
    for (int i = tid; i < 128 * 32; i += 256) {
        int r = i >> 5, c = i & 31;
        int vr = vbase + r; if (vr >= NV) vr = NV - 1;
        float4 v = ((const float4*)embed)[(size_t)vr * 32 + c];
        uint32_t h01, l01, h23, l23;
        split2(v.x, v.y, h01, l01);
        split2(v.z, v.w, h23, l23);
        uint32_t off = (uint32_t)(r * PKW + 4 * c) * 2;
        *(uint2*)(smem + P_AHI + off) = make_uint2(h01, h23);
        *(uint2*)(smem + P_ALO + off) = make_uint2(l01, l23);
    }
    __syncthreads();

    const int mrow = wid * 16;
    const int lrowB = ((l >> 4) & 1) * 8 + (l & 7);
    const int lkofB = 8 * ((l >> 3) & 1);
    const int lrowA = ((l >> 3) & 1) * 8 + (l & 7);
    const int lkofA = 8 * ((l >> 4) & 1);
    const int g = l >> 2, c2 = (l & 3) * 2;

    float d[16][4];
#pragma unroll
    for (int j = 0; j < 16; j++)
#pragma unroll
        for (int q = 0; q < 4; q++) d[j][q] = 0.f;

    // fused pass: B=Bhi, A = Ahi + Alo
#pragma unroll
    for (int kc = 0; kc < 8; kc++) {
        uint32_t ah[4], al[4];
        uint32_t aoff = (uint32_t)(((mrow + lrowA) * PKW + kc * 16 + lkofA) * 2);
        ldsm_x4(ah, sb + P_AHI + aoff);
        ldsm_x4(al, sb + P_ALO + aoff);
#pragma unroll
        for (int half = 0; half < 2; half++) {
            uint32_t b[16];
#pragma unroll
            for (int q = 0; q < 4; q++) {
                int ntp = half * 4 + q;
                ldsm_x4(b + 4 * q, sb + P_BHI + (uint32_t)(((ntp * 16 + lrowB) * PKW + kc * 16 + lkofB) * 2));
            }
#pragma unroll
            for (int q = 0; q < 4; q++) {
                int ntp = half * 4 + q;
                mma_op(d[2 * ntp],     ah, b[4 * q],     b[4 * q + 1]);
                mma_op(d[2 * ntp + 1], ah, b[4 * q + 2], b[4 * q + 3]);
                mma_op(d[2 * ntp],     al, b[4 * q],     b[4 * q + 1]);
                mma_op(d[2 * ntp + 1], al, b[4 * q + 2], b[4 * q + 3]);
            }
        }
    }
    // single pass: B=Blo, A=Ahi
#pragma unroll
    for (int kc = 0; kc < 8; kc++) {
        uint32_t ah[4];
        ldsm_x4(ah, sb + P_AHI + (uint32_t)(((mrow + lrowA) * PKW + kc * 16 + lkofA) * 2));
#pragma unroll
        for (int half = 0; half < 2; half++) {
            uint32_t b[16];
#pragma unroll
            for (int q = 0; q < 4; q++) {
                int ntp = half * 4 + q;
                ldsm_x4(b + 4 * q, sb + P_BLO + (uint32_t)(((ntp * 16 + lrowB) * PKW + kc * 16 + lkofB) * 2));
            }
#pragma unroll
            for (int q = 0; q < 4; q++) {
                int ntp = half * 4 + q;
                mma_op(d[2 * ntp],     ah, b[4 * q],     b[4 * q + 1]);
                mma_op(d[2 * ntp + 1], ah, b[4 * q + 2], b[4 * q + 3]);
            }
        }
    }

    // epilogue: + bias, store guarded rows to g_PE
    int row0 = vbase + mrow + g;
#pragma unroll
    for (int j = 0; j < 16; j++) {
        float2 bb = *(const float2*)(b1s + 8 * j + c2);
        float* o0 = g_PE + (size_t)row0 * HD + 8 * j + c2;
        *(float2*)o0 = make_float2(d[j][0] + bb.x, d[j][1] + bb.y);
        *(float2*)(o0 + 8 * HD) = make_float2(d[j][2] + bb.x, d[j][3] + bb.y);
    }
}

// =========================================================================
// Kernel 2 (scan): persistent register-fragment RNN; D-init gathers PE rows
// from L2. 128 CTAs x 256 thr (8 warps x 16 seqs). No syncthreads in loop.
// =========================================================================
#define S_W1HI 0
#define S_W1LO TILE_B
#define S_WIHI (2*TILE_B)
#define S_WILO (3*TILE_B)
#define S_W2HI (4*TILE_B)
#define S_W2LO (5*TILE_B)
#define S_B2   (6*TILE_B)
#define SCAN_SMEM (6*TILE_B + 512)

__global__ void __launch_bounds__(256, 1) scan_hmma_kernel(
    const int* __restrict__ x,
    const float* __restrict__ W_ih, const float* __restrict__ W_hh,
    const float* __restrict__ b_ih, const float* __restrict__ b_hh)
{
    extern __shared__ char smem[];
    const int tid = threadIdx.x;
    const int l = tid & 31, wid = tid >> 5;
    uint32_t sb = smem_u32(smem);

    load_wtile(W_hh,         smem + S_W1HI, smem + S_W1LO, tid, 256);   // Wh1
    load_wtile(W_ih + 16384, smem + S_WIHI, smem + S_WILO, tid, 256);   // Wi2
    load_wtile(W_hh + 16384, smem + S_W2HI, smem + S_W2LO, tid, 256);   // Wh2
    if (tid < 128) ((float*)(smem + S_B2))[tid] = b_ih[128 + tid] + b_hh[128 + tid];
    __syncthreads();

    const int lrowB = ((l >> 4) & 1) * 8 + (l & 7);
    const int lkofB = 8 * ((l >> 3) & 1);
    const int g = l >> 2, c2 = (l & 3) * 2;
    const int mrow = wid * 16;
    const size_t rowA = (size_t)(blockIdx.x * 128 + mrow + g);
    const float* b2s = (const float*)(smem + S_B2);

    const int* xa = x + rowA * SLEN;            // tokens of seq rowA
    const int* xb = x + (rowA + 8) * SLEN;      // tokens of seq rowA+8
    int tokA = xa[0], tokB = xb[0];

    uint32_t h1h[32], h1l[32], h2h[32], h2l[32];
#pragma unroll
    for (int i = 0; i < 32; i++) { h1h[i] = 0; h1l[i] = 0; h2h[i] = 0; h2l[i] = 0; }

    float d[16][4];

#pragma unroll 1
    for (int t = 0; t < SLEN; t++) {
        // ---- D init = PE[token] (L2-resident gather; b1 folded into PE) ----
        const float* pa = g_PE + (size_t)tokA * HD;
        const float* pb = g_PE + (size_t)tokB * HD;
#pragma unroll
        for (int j = 0; j < 16; j++) {
            float2 v0 = *(const float2*)(pa + 8 * j + c2);
            float2 v1 = *(const float2*)(pb + 8 * j + c2);
            d[j][0] = v0.x; d[j][1] = v0.y; d[j][2] = v1.x; d[j][3] = v1.y;
        }
        if (t + 1 < SLEN) { tokA = xa[t + 1]; tokB = xb[t + 1]; }

        // ---- layer 1: D += h1 x Wh1 (3-mult, B-shared) ----
        mma_pass2(d, h1h, h1l, sb + S_W1HI, lrowB, lkofB);
        mma_pass1(d, h1h,      sb + S_W1LO, lrowB, lkofB);

        // ---- epilogue 1: h1 = split(relu(D)) ----
#pragma unroll
        for (int kc = 0; kc < 8; kc++) {
            int j0 = 2 * kc, j1 = 2 * kc + 1;
            split2(fmaxf(d[j0][0], 0.f), fmaxf(d[j0][1], 0.f), h1h[4*kc+0], h1l[4*kc+0]);
            split2(fmaxf(d[j0][2], 0.f), fmaxf(d[j0][3], 0.f), h1h[4*kc+1], h1l[4*kc+1]);
            split2(fmaxf(d[j1][0], 0.f), fmaxf(d[j1][1], 0.f), h1h[4*kc+2], h1l[4*kc+2]);
            split2(fmaxf(d[j1][2], 0.f), fmaxf(d[j1][3], 0.f), h1h[4*kc+3], h1l[4*kc+3]);
        }

        // ---- layer 2: D = h1 x Wi2 + h2 x Wh2 (3-mult each, B-shared) ----
#pragma unroll
        for (int j = 0; j < 16; j++)
#pragma unroll
            for (int q = 0; q < 4; q++) d[j][q] = 0.f;
        mma_pass2(d, h1h, h1l, sb + S_WIHI, lrowB, lkofB);
        mma_pass1(d, h1h,      sb + S_WILO, lrowB, lkofB);
        mma_pass2(d, h2h, h2l, sb + S_W2HI, lrowB, lkofB);
        mma_pass1(d, h2h,      sb + S_W2LO, lrowB, lkofB);

        // ---- epilogue 2: h2 = split(relu(D + b2)); store g_h at last t ----
#pragma unroll
        for (int kc = 0; kc < 8; kc++) {
            int j0 = 2 * kc, j1 = 2 * kc + 1;
            float2 bb0 = *(const float2*)(b2s + 8 * j0 + c2);
            float2 bb1 = *(const float2*)(b2s + 8 * j1 + c2);
            float f00 = fmaxf(d[j0][0] + bb0.x, 0.f), f01 = fmaxf(d[j0][1] + bb0.y, 0.f);
            float f02 = fmaxf(d[j0][2] + bb0.x, 0.f), f03 = fmaxf(d[j0][3] + bb0.y, 0.f);
            float f10 = fmaxf(d[j1][0] + bb1.x, 0.f), f11 = fmaxf(d[j1][1] + bb1.y, 0.f);
            float f12 = fmaxf(d[j1][2] + bb1.x, 0.f), f13 = fmaxf(d[j1][3] + bb1.y, 0.f);
            split2(f00, f01, h2h[4*kc+0], h2l[4*kc+0]);
            split2(f02, f03, h2h[4*kc+1], h2l[4*kc+1]);
            split2(f10, f11, h2h[4*kc+2], h2l[4*kc+2]);
            split2(f12, f13, h2h[4*kc+3], h2l[4*kc+3]);
            if (t == SLEN - 1) {
                float* o0 = g_h + rowA * HD + 8 * j0 + c2;
                float* o1 = o0 + 8 * HD;
                *(float2*)o0 = make_float2(f00, f01);
                *(float2*)o1 = make_float2(f02, f03);
                *(float2*)(o0 + 8) = make_float2(f10, f11);
                *(float2*)(o1 + 8) = make_float2(f12, f13);
            }
        }
    }
}

// =========================================================================
// Kernel 3a: u[n] = w1.h[n], v[n] = w2.h[n]
// =========================================================================
__global__ void reduce1_kernel(const float* __restrict__ predW)
{
    int gwarp = (blockIdx.x * blockDim.x + threadIdx.x) >> 5;
    int lane = threadIdx.x & 31;
    if (gwarp >= NSEQ) return;
    const float* hr = g_h + (size_t)gwarp * 128;
    float su = 0.f, sv = 0.f;
#pragma unroll
    for (int i = 0; i < 4; i++) {
        int idx = lane + 32 * i;
        float hv = hr[idx];
        su += hv * predW[idx];
        sv += hv * predW[128 + idx];
    }
#pragma unroll
    for (int o = 16; o; o >>= 1) {
        su += __shfl_xor_sync(0xffffffffu, su, o);
        sv += __shfl_xor_sync(0xffffffffu, sv, o);
    }
    if (lane == 0) { g_u[gwarp] = su; g_v[gwarp] = sv; }
}

// =========================================================================
// Kernel 3b: out = u - 2v + rowsum(v) + colsum(v) + pred_b
// =========================================================================
__global__ void reduce2_kernel(const float* __restrict__ pred_b,
                               float* __restrict__ out)
{
    __shared__ float vs[NR * NC];
    __shared__ float RS[NR], CS[NC];
    const int b = blockIdx.x, tid = threadIdx.x;

    for (int i = tid; i < NR * NC; i += 256) vs[i] = g_v[b * NR * NC + i];
    __syncthreads();
    if (tid < NR) {
        float sr = 0.f;
        for (int c = 0; c < NC; c++) sr += vs[tid * NC + c];
        RS[tid] = sr;
    } else if (tid < NR + NC) {
        int c = tid - NR;
        float sc = 0.f;
        for (int r = 0; r < NR; r++) sc += vs[r * NC + c];
        CS[c] = sc;
    }
    __syncthreads();
    float pb = pred_b[0];
    for (int i = tid; i < NR * NC; i += 256) {
        int r = i >> 6, c = i & 63;
        out[b * NR * NC + i] =
            g_u[b * NR * NC + i] - 2.f * vs[i] + RS[r] + CS[c] + pb;
    }
}

// =========================================================================
extern "C" void kernel_launch(void* const* d_in, const int* in_sizes, int n_in,
                              void* d_out, int out_size)
{
    const int*   x      = (const int*)  d_in[0];
    const float* embed  = (const float*)d_in[1];
    const float* W_ih   = (const float*)d_in[2];
    const float* W_hh   = (const float*)d_in[3];
    const float* b_ih   = (const float*)d_in[4];
    const float* b_hh   = (const float*)d_in[5];
    const float* pred_W = (const float*)d_in[6];
    const float* pred_b = (const float*)d_in[7];
    float* out = (float*)d_out;

    cudaFuncSetAttribute(pe_hmma_kernel,   cudaFuncAttributeMaxDynamicSharedMemorySize, PROJ_SMEM);
    cudaFuncSetAttribute(scan_hmma_kernel, cudaFuncAttributeMaxDynamicSharedMemorySize, SCAN_SMEM);

    pe_hmma_kernel<<<NVPAD / 128, 256, PROJ_SMEM>>>(embed, W_ih, b_ih, b_hh);
    scan_hmma_kernel<<<128, 256, SCAN_SMEM>>>(x, W_ih, W_hh, b_ih, b_hh);
    reduce1_kernel<<<NSEQ / 8, 256>>>(pred_W);
    reduce2_kernel<<<NB, 256>>>(pred_b, out);
}

// round 8
// speedup vs baseline: 24.0178x; 1.4223x over previous
#include <cuda_runtime.h>
#include <cuda_fp16.h>
#include <cstdint>

#define NB 4
#define NR 64
#define NC 64
#define NSEQ 16384
#define SLEN 32
#define HD 128
#define NV 30000
#define NVPAD 30080             // 235 * 128
#define PKW 136                 // fp16 pitch of weight/A tiles (272B, LDSM conflict-free)
#define TILE_B (128*PKW*2)      // 34816 bytes per 128x128 fp16 tile

// ---------------- device scratch ----------------
__device__ float g_PE[(size_t)NVPAD * HD];     // 15.4 MB: embed @ Wi1^T + b1 (L2-resident)
__device__ float g_u[NSEQ];
__device__ float g_v[NSEQ];

// ================= helpers =================
__device__ __forceinline__ uint32_t smem_u32(const void* p) {
    uint32_t a;
    asm("{ .reg .u64 t; cvta.to.shared.u64 t, %1; cvt.u32.u64 %0, t; }" : "=r"(a) : "l"(p));
    return a;
}
__device__ __forceinline__ void ldsm_x4(uint32_t* r, uint32_t addr) {
    asm volatile("ldmatrix.sync.aligned.m8n8.x4.shared.b16 {%0,%1,%2,%3}, [%4];"
        : "=r"(r[0]), "=r"(r[1]), "=r"(r[2]), "=r"(r[3]) : "r"(addr));
}
__device__ __forceinline__ void mma_op(float* d, const uint32_t* a, uint32_t b0, uint32_t b1) {
    asm volatile("mma.sync.aligned.m16n8k16.row.col.f32.f16.f16.f32 "
        "{%0,%1,%2,%3}, {%4,%5,%6,%7}, {%8,%9}, {%0,%1,%2,%3};"
        : "+f"(d[0]), "+f"(d[1]), "+f"(d[2]), "+f"(d[3])
        : "r"(a[0]), "r"(a[1]), "r"(a[2]), "r"(a[3]), "r"(b0), "r"(b1));
}
// split (f0,f1) into fp16 hi pair + residual lo pair
__device__ __forceinline__ void split2h(float f0, float f1, uint32_t& hi, uint32_t& lo) {
    __half h0 = __float2half_rn(f0), h1 = __float2half_rn(f1);
    float l0 = f0 - __half2float(h0), l1 = f1 - __half2float(h1);
    __half2 hp = __halves2half2(h0, h1);
    __half2 lp = __halves2half2(__float2half_rn(l0), __float2half_rn(l1));
    hi = *reinterpret_cast<uint32_t*>(&hp);
    lo = *reinterpret_cast<uint32_t*>(&lp);
}
// load fp32 W[128][128] -> single fp16 tile stored [n][k] pitch PKW
__device__ void load_wtile_h(const float* __restrict__ W, char* dst, int tid, int nthr) {
    for (int i = tid; i < 16384; i += nthr) {
        int n = i >> 7, k = i & 127;
        *reinterpret_cast<__half*>(dst + (n * PKW + k) * 2) = __float2half_rn(W[i]);
    }
}

// Dual-A pass: D += (A0 + A1) x B — B fragments loaded ONCE
__device__ __forceinline__ void mma_pass2(float (*d)[4], const uint32_t* a0, const uint32_t* a1,
                                          uint32_t wb, int lrowB, int lkofB)
{
#pragma unroll
    for (int kc = 0; kc < 8; kc++) {
#pragma unroll
        for (int half = 0; half < 2; half++) {
            uint32_t b[16];
#pragma unroll
            for (int q = 0; q < 4; q++) {
                int ntp = half * 4 + q;
                ldsm_x4(b + 4 * q, wb + (uint32_t)(((ntp * 16 + lrowB) * PKW + kc * 16 + lkofB) * 2));
            }
#pragma unroll
            for (int q = 0; q < 4; q++) {
                int ntp = half * 4 + q;
                mma_op(d[2 * ntp],     a0 + 4 * kc, b[4 * q],     b[4 * q + 1]);
                mma_op(d[2 * ntp + 1], a0 + 4 * kc, b[4 * q + 2], b[4 * q + 3]);
                mma_op(d[2 * ntp],     a1 + 4 * kc, b[4 * q],     b[4 * q + 1]);
                mma_op(d[2 * ntp + 1], a1 + 4 * kc, b[4 * q + 2], b[4 * q + 3]);
            }
        }
    }
}

// =========================================================================
// Kernel 1 (PE): PE[v][h] = embed[v] @ Wi1^T + (bi1+bh1)
// 235 CTAs x 256 thr; A = embed split fp16 hi/lo, B = Wi1 single fp16.
// =========================================================================
#define P_AHI 0
#define P_ALO TILE_B
#define P_B   (2*TILE_B)
#define P_B1  (3*TILE_B)
#define PROJ_SMEM (3*TILE_B + 1024)

__global__ void __launch_bounds__(256, 1) pe_hmma_kernel(
    const float* __restrict__ embed, const float* __restrict__ W_ih,
    const float* __restrict__ b_ih, const float* __restrict__ b_hh)
{
    extern __shared__ char smem[];
    const int tid = threadIdx.x;
    const int l = tid & 31, wid = tid >> 5;
    uint32_t sb = smem_u32(smem);

    const int vbase = blockIdx.x * 128;

    load_wtile_h(W_ih, smem + P_B, tid, 256);
    if (tid < 128) ((float*)(smem + P_B1))[tid] = b_ih[tid] + b_hh[tid];
    const float* b1s = (const float*)(smem + P_B1);

    // A tile = 128 consecutive vocab embedding rows (guarded), fp16 hi/lo
    for (int i = tid; i < 128 * 32; i += 256) {
        int r = i >> 5, c = i & 31;
        int vr = vbase + r; if (vr >= NV) vr = NV - 1;
        float4 v = ((const float4*)embed)[(size_t)vr * 32 + c];
        uint32_t h01, l01, h23, l23;
        split2h(v.x, v.y, h01, l01);
        split2h(v.z, v.w, h23, l23);
        uint32_t off = (uint32_t)(r * PKW + 4 * c) * 2;
        *(uint2*)(smem + P_AHI + off) = make_uint2(h01, h23);
        *(uint2*)(smem + P_ALO + off) = make_uint2(l01, l23);
    }
    __syncthreads();

    const int mrow = wid * 16;
    const int lrowB = ((l >> 4) & 1) * 8 + (l & 7);
    const int lkofB = 8 * ((l >> 3) & 1);
    const int lrowA = ((l >> 3) & 1) * 8 + (l & 7);
    const int lkofA = 8 * ((l >> 4) & 1);
    const int g = l >> 2, c2 = (l & 3) * 2;

    float d[16][4];
#pragma unroll
    for (int j = 0; j < 16; j++)
#pragma unroll
        for (int q = 0; q < 4; q++) d[j][q] = 0.f;

    // fused 2-mult pass: B loaded once, A = Ahi + Alo
#pragma unroll
    for (int kc = 0; kc < 8; kc++) {
        uint32_t ah[4], al[4];
        uint32_t aoff = (uint32_t)(((mrow + lrowA) * PKW + kc * 16 + lkofA) * 2);
        ldsm_x4(ah, sb + P_AHI + aoff);
        ldsm_x4(al, sb + P_ALO + aoff);
#pragma unroll
        for (int half = 0; half < 2; half++) {
            uint32_t b[16];
#pragma unroll
            for (int q = 0; q < 4; q++) {
                int ntp = half * 4 + q;
                ldsm_x4(b + 4 * q, sb + P_B + (uint32_t)(((ntp * 16 + lrowB) * PKW + kc * 16 + lkofB) * 2));
            }
#pragma unroll
            for (int q = 0; q < 4; q++) {
                int ntp = half * 4 + q;
                mma_op(d[2 * ntp],     ah, b[4 * q],     b[4 * q + 1]);
                mma_op(d[2 * ntp + 1], ah, b[4 * q + 2], b[4 * q + 3]);
                mma_op(d[2 * ntp],     al, b[4 * q],     b[4 * q + 1]);
                mma_op(d[2 * ntp + 1], al, b[4 * q + 2], b[4 * q + 3]);
            }
        }
    }

    // epilogue: + bias, store to g_PE
    int row0 = vbase + mrow + g;
#pragma unroll
    for (int j = 0; j < 16; j++) {
        float2 bb = *(const float2*)(b1s + 8 * j + c2);
        float* o0 = g_PE + (size_t)row0 * HD + 8 * j + c2;
        *(float2*)o0 = make_float2(d[j][0] + bb.x, d[j][1] + bb.y);
        *(float2*)(o0 + 8 * HD) = make_float2(d[j][2] + bb.x, d[j][3] + bb.y);
    }
}

// =========================================================================
// Kernel 2 (scan): persistent register-fragment RNN, fp16 h-split (2-mult),
// single-fp16 weights, fused u/v head. 128 CTAs x 256 thr.
// =========================================================================
#define S_W1  0
#define S_WI  TILE_B
#define S_W2  (2*TILE_B)
#define S_B2  (3*TILE_B)
#define S_PW  (3*TILE_B + 512)
#define SCAN_SMEM (3*TILE_B + 512 + 1024)

__global__ void __launch_bounds__(256, 1) scan_hmma_kernel(
    const int* __restrict__ x,
    const float* __restrict__ W_ih, const float* __restrict__ W_hh,
    const float* __restrict__ b_ih, const float* __restrict__ b_hh,
    const float* __restrict__ pred_W)
{
    extern __shared__ char smem[];
    const int tid = threadIdx.x;
    const int l = tid & 31, wid = tid >> 5;
    uint32_t sb = smem_u32(smem);

    load_wtile_h(W_hh,         smem + S_W1, tid, 256);   // Wh1
    load_wtile_h(W_ih + 16384, smem + S_WI, tid, 256);   // Wi2
    load_wtile_h(W_hh + 16384, smem + S_W2, tid, 256);   // Wh2
    if (tid < 128) ((float*)(smem + S_B2))[tid] = b_ih[128 + tid] + b_hh[128 + tid];
    if (tid < 256) ((float*)(smem + S_PW))[tid] = pred_W[tid];
    __syncthreads();

    const int lrowB = ((l >> 4) & 1) * 8 + (l & 7);
    const int lkofB = 8 * ((l >> 3) & 1);
    const int g = l >> 2, c2 = (l & 3) * 2;
    const int mrow = wid * 16;
    const size_t rowA = (size_t)(blockIdx.x * 128 + mrow + g);
    const float* b2s = (const float*)(smem + S_B2);
    const float* pw1 = (const float*)(smem + S_PW);
    const float* pw2 = pw1 + 128;

    const int* xa = x + rowA * SLEN;            // tokens of seq rowA
    const int* xb = x + (rowA + 8) * SLEN;      // tokens of seq rowA+8
    int tokA = xa[0], tokB = xb[0];

    uint32_t h1h[32], h1l[32], h2h[32], h2l[32];
#pragma unroll
    for (int i = 0; i < 32; i++) { h1h[i] = 0; h1l[i] = 0; h2h[i] = 0; h2l[i] = 0; }

    float d[16][4];
    float u_a = 0.f, v_a = 0.f, u_b = 0.f, v_b = 0.f;

#pragma unroll 1
    for (int t = 0; t < SLEN; t++) {
        // ---- D init = PE[token] (L2-resident gather; b1 folded into PE) ----
        const float* pa = g_PE + (size_t)tokA * HD;
        const float* pb = g_PE + (size_t)tokB * HD;
#pragma unroll
        for (int j = 0; j < 16; j++) {
            float2 v0 = *(const float2*)(pa + 8 * j + c2);
            float2 v1 = *(const float2*)(pb + 8 * j + c2);
            d[j][0] = v0.x; d[j][1] = v0.y; d[j][2] = v1.x; d[j][3] = v1.y;
        }
        if (t + 1 < SLEN) { tokA = xa[t + 1]; tokB = xb[t + 1]; }

        // ---- layer 1: D += (h1h + h1l) x Wh1 (one B stream) ----
        mma_pass2(d, h1h, h1l, sb + S_W1, lrowB, lkofB);

        // ---- epilogue 1: h1 = split(relu(D)) ----
#pragma unroll
        for (int kc = 0; kc < 8; kc++) {
            int j0 = 2 * kc, j1 = 2 * kc + 1;
            split2h(fmaxf(d[j0][0], 0.f), fmaxf(d[j0][1], 0.f), h1h[4*kc+0], h1l[4*kc+0]);
            split2h(fmaxf(d[j0][2], 0.f), fmaxf(d[j0][3], 0.f), h1h[4*kc+1], h1l[4*kc+1]);
            split2h(fmaxf(d[j1][0], 0.f), fmaxf(d[j1][1], 0.f), h1h[4*kc+2], h1l[4*kc+2]);
            split2h(fmaxf(d[j1][2], 0.f), fmaxf(d[j1][3], 0.f), h1h[4*kc+3], h1l[4*kc+3]);
        }

        // ---- layer 2: D = (h1h+h1l) x Wi2 + (h2h+h2l) x Wh2 ----
#pragma unroll
        for (int j = 0; j < 16; j++)
#pragma unroll
            for (int q = 0; q < 4; q++) d[j][q] = 0.f;
        mma_pass2(d, h1h, h1l, sb + S_WI, lrowB, lkofB);
        mma_pass2(d, h2h, h2l, sb + S_W2, lrowB, lkofB);

        // ---- epilogue 2: h2 = split(relu(D + b2)); fused u/v head at last t ----
#pragma unroll
        for (int kc = 0; kc < 8; kc++) {
            int j0 = 2 * kc, j1 = 2 * kc + 1;
            float2 bb0 = *(const float2*)(b2s + 8 * j0 + c2);
            float2 bb1 = *(const float2*)(b2s + 8 * j1 + c2);
            float f00 = fmaxf(d[j0][0] + bb0.x, 0.f), f01 = fmaxf(d[j0][1] + bb0.y, 0.f);
            float f02 = fmaxf(d[j0][2] + bb0.x, 0.f), f03 = fmaxf(d[j0][3] + bb0.y, 0.f);
            float f10 = fmaxf(d[j1][0] + bb1.x, 0.f), f11 = fmaxf(d[j1][1] + bb1.y, 0.f);
            float f12 = fmaxf(d[j1][2] + bb1.x, 0.f), f13 = fmaxf(d[j1][3] + bb1.y, 0.f);
            split2h(f00, f01, h2h[4*kc+0], h2l[4*kc+0]);
            split2h(f02, f03, h2h[4*kc+1], h2l[4*kc+1]);
            split2h(f10, f11, h2h[4*kc+2], h2l[4*kc+2]);
            split2h(f12, f13, h2h[4*kc+3], h2l[4*kc+3]);
            if (t == SLEN - 1) {
                int c0 = 8 * j0 + c2, c1 = 8 * j1 + c2;
                u_a += pw1[c0] * f00 + pw1[c0 + 1] * f01 + pw1[c1] * f10 + pw1[c1 + 1] * f11;
                u_b += pw1[c0] * f02 + pw1[c0 + 1] * f03 + pw1[c1] * f12 + pw1[c1 + 1] * f13;
                v_a += pw2[c0] * f00 + pw2[c0 + 1] * f01 + pw2[c1] * f10 + pw2[c1 + 1] * f11;
                v_b += pw2[c0] * f02 + pw2[c0 + 1] * f03 + pw2[c1] * f12 + pw2[c1 + 1] * f13;
            }
        }
    }

    // quad reduction over the 4 lanes sharing each row (c2 = 0,2,4,6)
#pragma unroll
    for (int o = 1; o <= 2; o <<= 1) {
        u_a += __shfl_xor_sync(0xffffffffu, u_a, o);
        u_b += __shfl_xor_sync(0xffffffffu, u_b, o);
        v_a += __shfl_xor_sync(0xffffffffu, v_a, o);
        v_b += __shfl_xor_sync(0xffffffffu, v_b, o);
    }
    if ((l & 3) == 0) {
        g_u[rowA] = u_a;     g_v[rowA] = v_a;
        g_u[rowA + 8] = u_b; g_v[rowA + 8] = v_b;
    }
}

// =========================================================================
// Kernel 3: out = u - 2v + rowsum(v) + colsum(v) + pred_b
// =========================================================================
__global__ void reduce2_kernel(const float* __restrict__ pred_b,
                               float* __restrict__ out)
{
    __shared__ float vs[NR * NC];
    __shared__ float RS[NR], CS[NC];
    const int b = blockIdx.x, tid = threadIdx.x;

    for (int i = tid; i < NR * NC; i += 256) vs[i] = g_v[b * NR * NC + i];
    __syncthreads();
    if (tid < NR) {
        float sr = 0.f;
        for (int c = 0; c < NC; c++) sr += vs[tid * NC + c];
        RS[tid] = sr;
    } else if (tid < NR + NC) {
        int c = tid - NR;
        float sc = 0.f;
        for (int r = 0; r < NR; r++) sc += vs[r * NC + c];
        CS[c] = sc;
    }
    __syncthreads();
    float pb = pred_b[0];
    for (int i = tid; i < NR * NC; i += 256) {
        int r = i >> 6, c = i & 63;
        out[b * NR * NC + i] =
            g_u[b * NR * NC + i] - 2.f * vs[i] + RS[r] + CS[c] + pb;
    }
}

// =========================================================================
extern "C" void kernel_launch(void* const* d_in, const int* in_sizes, int n_in,
                              void* d_out, int out_size)
{
    const int*   x      = (const int*)  d_in[0];
    const float* embed  = (const float*)d_in[1];
    const float* W_ih   = (const float*)d_in[2];
    const float* W_hh   = (const float*)d_in[3];
    const float* b_ih   = (const float*)d_in[4];
    const float* b_hh   = (const float*)d_in[5];
    const float* pred_W = (const float*)d_in[6];
    const float* pred_b = (const float*)d_in[7];
    float* out = (float*)d_out;

    cudaFuncSetAttribute(pe_hmma_kernel,   cudaFuncAttributeMaxDynamicSharedMemorySize, PROJ_SMEM);
    cudaFuncSetAttribute(scan_hmma_kernel, cudaFuncAttributeMaxDynamicSharedMemorySize, SCAN_SMEM);

    pe_hmma_kernel<<<NVPAD / 128, 256, PROJ_SMEM>>>(embed, W_ih, b_ih, b_hh);
    scan_hmma_kernel<<<128, 256, SCAN_SMEM>>>(x, W_ih, W_hh, b_ih, b_hh, pred_W);
    reduce2_kernel<<<NB, 256>>>(pred_b, out);
}

// round 9
// speedup vs baseline: 24.0206x; 1.0001x over previous
#include <cuda_runtime.h>
#include <cuda_fp16.h>
#include <cstdint>

#define NB 4
#define NR 64
#define NC 64
#define NSEQ 16384
#define SLEN 32
#define HD 128
#define NV 30000
#define NVPAD 30080             // 470 * 64
#define PKW 136                 // fp16 pitch of weight/A tiles (272B, LDSM conflict-free)
#define TILE_B (128*PKW*2)      // 34816 bytes per 128x128 fp16 tile
#define TILE_A64 (64*PKW*2)     // 17408 bytes per 64x128 fp16 tile

// ---------------- device scratch ----------------
__device__ float g_PE[(size_t)NVPAD * HD];     // 15.4 MB: embed @ Wi1^T + b1 (L2-resident)
__device__ float g_u[NSEQ];
__device__ float g_v[NSEQ];

// ================= helpers =================
__device__ __forceinline__ uint32_t smem_u32(const void* p) {
    uint32_t a;
    asm("{ .reg .u64 t; cvta.to.shared.u64 t, %1; cvt.u32.u64 %0, t; }" : "=r"(a) : "l"(p));
    return a;
}
__device__ __forceinline__ void ldsm_x4(uint32_t* r, uint32_t addr) {
    asm volatile("ldmatrix.sync.aligned.m8n8.x4.shared.b16 {%0,%1,%2,%3}, [%4];"
        : "=r"(r[0]), "=r"(r[1]), "=r"(r[2]), "=r"(r[3]) : "r"(addr));
}
__device__ __forceinline__ void mma_op(float* d, const uint32_t* a, uint32_t b0, uint32_t b1) {
    asm volatile("mma.sync.aligned.m16n8k16.row.col.f32.f16.f16.f32 "
        "{%0,%1,%2,%3}, {%4,%5,%6,%7}, {%8,%9}, {%0,%1,%2,%3};"
        : "+f"(d[0]), "+f"(d[1]), "+f"(d[2]), "+f"(d[3])
        : "r"(a[0]), "r"(a[1]), "r"(a[2]), "r"(a[3]), "r"(b0), "r"(b1));
}
// split (f0,f1) into fp16 hi pair + residual lo pair
__device__ __forceinline__ void split2h(float f0, float f1, uint32_t& hi, uint32_t& lo) {
    __half h0 = __float2half_rn(f0), h1 = __float2half_rn(f1);
    float l0 = f0 - __half2float(h0), l1 = f1 - __half2float(h1);
    __half2 hp = __halves2half2(h0, h1);
    __half2 lp = __halves2half2(__float2half_rn(l0), __float2half_rn(l1));
    hi = *reinterpret_cast<uint32_t*>(&hp);
    lo = *reinterpret_cast<uint32_t*>(&lp);
}
// load fp32 W[128][128] -> single fp16 tile stored [n][k] pitch PKW
__device__ void load_wtile_h(const float* __restrict__ W, char* dst, int tid, int nthr) {
    for (int i = tid; i < 16384; i += nthr) {
        int n = i >> 7, k = i & 127;
        *reinterpret_cast<__half*>(dst + (n * PKW + k) * 2) = __float2half_rn(W[i]);
    }
}

// Dual-A pass: D += (A0 + A1) x B — B fragments loaded ONCE
__device__ __forceinline__ void mma_pass2(float (*d)[4], const uint32_t* a0, const uint32_t* a1,
                                          uint32_t wb, int lrowB, int lkofB)
{
#pragma unroll
    for (int kc = 0; kc < 8; kc++) {
#pragma unroll
        for (int half = 0; half < 2; half++) {
            uint32_t b[16];
#pragma unroll
            for (int q = 0; q < 4; q++) {
                int ntp = half * 4 + q;
                ldsm_x4(b + 4 * q, wb + (uint32_t)(((ntp * 16 + lrowB) * PKW + kc * 16 + lkofB) * 2));
            }
#pragma unroll
            for (int q = 0; q < 4; q++) {
                int ntp = half * 4 + q;
                mma_op(d[2 * ntp],     a0 + 4 * kc, b[4 * q],     b[4 * q + 1]);
                mma_op(d[2 * ntp + 1], a0 + 4 * kc, b[4 * q + 2], b[4 * q + 3]);
                mma_op(d[2 * ntp],     a1 + 4 * kc, b[4 * q],     b[4 * q + 1]);
                mma_op(d[2 * ntp + 1], a1 + 4 * kc, b[4 * q + 2], b[4 * q + 3]);
            }
        }
    }
}

// =========================================================================
// Kernel 1 (PE): PE[v][h] = embed[v] @ Wi1^T + (bi1+bh1)
// 470 CTAs x 128 thr (4 warps), 64-row tiles, 3 CTAs/SM for gather MLP.
// =========================================================================
#define P_AHI 0
#define P_ALO TILE_A64
#define P_B   (2*TILE_A64)
#define P_B1  (2*TILE_A64 + TILE_B)
#define PROJ_SMEM (2*TILE_A64 + TILE_B + 512)

__global__ void __launch_bounds__(128, 3) pe_hmma_kernel(
    const float* __restrict__ embed, const float* __restrict__ W_ih,
    const float* __restrict__ b_ih, const float* __restrict__ b_hh)
{
    extern __shared__ char smem[];
    const int tid = threadIdx.x;
    const int l = tid & 31, wid = tid >> 5;
    uint32_t sb = smem_u32(smem);

    const int vbase = blockIdx.x * 64;

    load_wtile_h(W_ih, smem + P_B, tid, 128);
    ((float*)(smem + P_B1))[tid] = b_ih[tid] + b_hh[tid];
    const float* b1s = (const float*)(smem + P_B1);

    // A tile = 64 consecutive vocab embedding rows (guarded), fp16 hi/lo
    for (int i = tid; i < 64 * 32; i += 128) {
        int r = i >> 5, c = i & 31;
        int vr = vbase + r; if (vr >= NV) vr = NV - 1;
        float4 v = ((const float4*)embed)[(size_t)vr * 32 + c];
        uint32_t h01, l01, h23, l23;
        split2h(v.x, v.y, h01, l01);
        split2h(v.z, v.w, h23, l23);
        uint32_t off = (uint32_t)(r * PKW + 4 * c) * 2;
        *(uint2*)(smem + P_AHI + off) = make_uint2(h01, h23);
        *(uint2*)(smem + P_ALO + off) = make_uint2(l01, l23);
    }
    __syncthreads();

    const int mrow = wid * 16;
    const int lrowB = ((l >> 4) & 1) * 8 + (l & 7);
    const int lkofB = 8 * ((l >> 3) & 1);
    const int lrowA = ((l >> 3) & 1) * 8 + (l & 7);
    const int lkofA = 8 * ((l >> 4) & 1);
    const int g = l >> 2, c2 = (l & 3) * 2;

    float d[16][4];
#pragma unroll
    for (int j = 0; j < 16; j++)
#pragma unroll
        for (int q = 0; q < 4; q++) d[j][q] = 0.f;

    // fused 2-mult pass: B loaded once, A = Ahi + Alo
#pragma unroll
    for (int kc = 0; kc < 8; kc++) {
        uint32_t ah[4], al[4];
        uint32_t aoff = (uint32_t)(((mrow + lrowA) * PKW + kc * 16 + lkofA) * 2);
        ldsm_x4(ah, sb + P_AHI + aoff);
        ldsm_x4(al, sb + P_ALO + aoff);
#pragma unroll
        for (int half = 0; half < 2; half++) {
            uint32_t b[16];
#pragma unroll
            for (int q = 0; q < 4; q++) {
                int ntp = half * 4 + q;
                ldsm_x4(b + 4 * q, sb + P_B + (uint32_t)(((ntp * 16 + lrowB) * PKW + kc * 16 + lkofB) * 2));
            }
#pragma unroll
            for (int q = 0; q < 4; q++) {
                int ntp = half * 4 + q;
                mma_op(d[2 * ntp],     ah, b[4 * q],     b[4 * q + 1]);
                mma_op(d[2 * ntp + 1], ah, b[4 * q + 2], b[4 * q + 3]);
                mma_op(d[2 * ntp],     al, b[4 * q],     b[4 * q + 1]);
                mma_op(d[2 * ntp + 1], al, b[4 * q + 2], b[4 * q + 3]);
            }
        }
    }

    // epilogue: + bias, store to g_PE
    int row0 = vbase + mrow + g;
#pragma unroll
    for (int j = 0; j < 16; j++) {
        float2 bb = *(const float2*)(b1s + 8 * j + c2);
        float* o0 = g_PE + (size_t)row0 * HD + 8 * j + c2;
        *(float2*)o0 = make_float2(d[j][0] + bb.x, d[j][1] + bb.y);
        *(float2*)(o0 + 8 * HD) = make_float2(d[j][2] + bb.x, d[j][3] + bb.y);
    }
}

// =========================================================================
// Kernel 2 (scan): persistent register-fragment RNN, fp16 h-split (2-mult),
// single-fp16 weights, fused u/v head. 128 CTAs x 256 thr.
// =========================================================================
#define S_W1  0
#define S_WI  TILE_B
#define S_W2  (2*TILE_B)
#define S_B2  (3*TILE_B)
#define S_PW  (3*TILE_B + 512)
#define SCAN_SMEM (3*TILE_B + 512 + 1024)

__global__ void __launch_bounds__(256, 1) scan_hmma_kernel(
    const int* __restrict__ x,
    const float* __restrict__ W_ih, const float* __restrict__ W_hh,
    const float* __restrict__ b_ih, const float* __restrict__ b_hh,
    const float* __restrict__ pred_W)
{
    extern __shared__ char smem[];
    const int tid = threadIdx.x;
    const int l = tid & 31, wid = tid >> 5;
    uint32_t sb = smem_u32(smem);

    load_wtile_h(W_hh,         smem + S_W1, tid, 256);   // Wh1
    load_wtile_h(W_ih + 16384, smem + S_WI, tid, 256);   // Wi2
    load_wtile_h(W_hh + 16384, smem + S_W2, tid, 256);   // Wh2
    if (tid < 128) ((float*)(smem + S_B2))[tid] = b_ih[128 + tid] + b_hh[128 + tid];
    if (tid < 256) ((float*)(smem + S_PW))[tid] = pred_W[tid];
    __syncthreads();

    const int lrowB = ((l >> 4) & 1) * 8 + (l & 7);
    const int lkofB = 8 * ((l >> 3) & 1);
    const int g = l >> 2, c2 = (l & 3) * 2;
    const int mrow = wid * 16;
    const size_t rowA = (size_t)(blockIdx.x * 128 + mrow + g);
    const float* b2s = (const float*)(smem + S_B2);
    const float* pw1 = (const float*)(smem + S_PW);
    const float* pw2 = pw1 + 128;

    const int* xa = x + rowA * SLEN;            // tokens of seq rowA
    const int* xb = x + (rowA + 8) * SLEN;      // tokens of seq rowA+8
    int tokA = xa[0], tokB = xb[0];

    uint32_t h1h[32], h1l[32], h2h[32], h2l[32];
#pragma unroll
    for (int i = 0; i < 32; i++) { h1h[i] = 0; h1l[i] = 0; h2h[i] = 0; h2l[i] = 0; }

    float d[16][4];
    float u_a = 0.f, v_a = 0.f, u_b = 0.f, v_b = 0.f;

#pragma unroll 1
    for (int t = 0; t < SLEN; t++) {
        // ---- D init = PE[token] (L2-resident gather; b1 folded into PE) ----
        const float* pa = g_PE + (size_t)tokA * HD;
        const float* pb = g_PE + (size_t)tokB * HD;
#pragma unroll
        for (int j = 0; j < 16; j++) {
            float2 v0 = *(const float2*)(pa + 8 * j + c2);
            float2 v1 = *(const float2*)(pb + 8 * j + c2);
            d[j][0] = v0.x; d[j][1] = v0.y; d[j][2] = v1.x; d[j][3] = v1.y;
        }
        if (t + 1 < SLEN) { tokA = xa[t + 1]; tokB = xb[t + 1]; }

        // ---- layer 1: D += (h1h + h1l) x Wh1 (one B stream) ----
        mma_pass2(d, h1h, h1l, sb + S_W1, lrowB, lkofB);

        // ---- epilogue 1: h1 = split(relu(D)) ----
#pragma unroll
        for (int kc = 0; kc < 8; kc++) {
            int j0 = 2 * kc, j1 = 2 * kc + 1;
            split2h(fmaxf(d[j0][0], 0.f), fmaxf(d[j0][1], 0.f), h1h[4*kc+0], h1l[4*kc+0]);
            split2h(fmaxf(d[j0][2], 0.f), fmaxf(d[j0][3], 0.f), h1h[4*kc+1], h1l[4*kc+1]);
            split2h(fmaxf(d[j1][0], 0.f), fmaxf(d[j1][1], 0.f), h1h[4*kc+2], h1l[4*kc+2]);
            split2h(fmaxf(d[j1][2], 0.f), fmaxf(d[j1][3], 0.f), h1h[4*kc+3], h1l[4*kc+3]);
        }

        // ---- layer 2: D = (h1h+h1l) x Wi2 + (h2h+h2l) x Wh2 ----
#pragma unroll
        for (int j = 0; j < 16; j++)
#pragma unroll
            for (int q = 0; q < 4; q++) d[j][q] = 0.f;
        mma_pass2(d, h1h, h1l, sb + S_WI, lrowB, lkofB);
        mma_pass2(d, h2h, h2l, sb + S_W2, lrowB, lkofB);

        // ---- epilogue 2: h2 = split(relu(D + b2)); fused u/v head at last t ----
#pragma unroll
        for (int kc = 0; kc < 8; kc++) {
            int j0 = 2 * kc, j1 = 2 * kc + 1;
            float2 bb0 = *(const float2*)(b2s + 8 * j0 + c2);
            float2 bb1 = *(const float2*)(b2s + 8 * j1 + c2);
            float f00 = fmaxf(d[j0][0] + bb0.x, 0.f), f01 = fmaxf(d[j0][1] + bb0.y, 0.f);
            float f02 = fmaxf(d[j0][2] + bb0.x, 0.f), f03 = fmaxf(d[j0][3] + bb0.y, 0.f);
            float f10 = fmaxf(d[j1][0] + bb1.x, 0.f), f11 = fmaxf(d[j1][1] + bb1.y, 0.f);
            float f12 = fmaxf(d[j1][2] + bb1.x, 0.f), f13 = fmaxf(d[j1][3] + bb1.y, 0.f);
            split2h(f00, f01, h2h[4*kc+0], h2l[4*kc+0]);
            split2h(f02, f03, h2h[4*kc+1], h2l[4*kc+1]);
            split2h(f10, f11, h2h[4*kc+2], h2l[4*kc+2]);
            split2h(f12, f13, h2h[4*kc+3], h2l[4*kc+3]);
            if (t == SLEN - 1) {
                int c0 = 8 * j0 + c2, c1 = 8 * j1 + c2;
                u_a += pw1[c0] * f00 + pw1[c0 + 1] * f01 + pw1[c1] * f10 + pw1[c1 + 1] * f11;
                u_b += pw1[c0] * f02 + pw1[c0 + 1] * f03 + pw1[c1] * f12 + pw1[c1 + 1] * f13;
                v_a += pw2[c0] * f00 + pw2[c0 + 1] * f01 + pw2[c1] * f10 + pw2[c1 + 1] * f11;
                v_b += pw2[c0] * f02 + pw2[c0 + 1] * f03 + pw2[c1] * f12 + pw2[c1 + 1] * f13;
            }
        }
    }

    // quad reduction over the 4 lanes sharing each row (c2 = 0,2,4,6)
#pragma unroll
    for (int o = 1; o <= 2; o <<= 1) {
        u_a += __shfl_xor_sync(0xffffffffu, u_a, o);
        u_b += __shfl_xor_sync(0xffffffffu, u_b, o);
        v_a += __shfl_xor_sync(0xffffffffu, v_a, o);
        v_b += __shfl_xor_sync(0xffffffffu, v_b, o);
    }
    if ((l & 3) == 0) {
        g_u[rowA] = u_a;     g_v[rowA] = v_a;
        g_u[rowA + 8] = u_b; g_v[rowA + 8] = v_b;
    }
}

// =========================================================================
// Kernel 3: out = u - 2v + rowsum(v) + colsum(v) + pred_b
// grid NB x 1024 thr; warp-per-row/col shuffle reductions; pitch-65 smem.
// =========================================================================
__global__ void __launch_bounds__(1024, 1) reduce2_kernel(
    const float* __restrict__ pred_b, float* __restrict__ out)
{
    __shared__ float vs[64 * 65];
    __shared__ float RS[64], CS[64];
    const int b = blockIdx.x, tid = threadIdx.x;
    const int w = tid >> 5, l = tid & 31;

    for (int i = tid; i < 4096; i += 1024)
        vs[(i >> 6) * 65 + (i & 63)] = g_v[b * 4096 + i];
    __syncthreads();

    // row sums: warp w -> rows w, w+32
    float r0 = vs[w * 65 + l] + vs[w * 65 + l + 32];
    float r1 = vs[(w + 32) * 65 + l] + vs[(w + 32) * 65 + l + 32];
    // col sums: warp w -> cols w, w+32 (pitch 65 => conflict-free)
    float q0 = vs[l * 65 + w] + vs[(l + 32) * 65 + w];
    float q1 = vs[l * 65 + w + 32] + vs[(l + 32) * 65 + w + 32];
#pragma unroll
    for (int o = 16; o; o >>= 1) {
        r0 += __shfl_xor_sync(0xffffffffu, r0, o);
        r1 += __shfl_xor_sync(0xffffffffu, r1, o);
        q0 += __shfl_xor_sync(0xffffffffu, q0, o);
        q1 += __shfl_xor_sync(0xffffffffu, q1, o);
    }
    if (l == 0) { RS[w] = r0; RS[w + 32] = r1; CS[w] = q0; CS[w + 32] = q1; }
    __syncthreads();

    float pb = pred_b[0];
    for (int i = tid; i < 4096; i += 1024) {
        int r = i >> 6, c = i & 63;
        out[b * 4096 + i] =
            g_u[b * 4096 + i] - 2.f * vs[r * 65 + c] + RS[r] + CS[c] + pb;
    }
}

// =========================================================================
extern "C" void kernel_launch(void* const* d_in, const int* in_sizes, int n_in,
                              void* d_out, int out_size)
{
    const int*   x      = (const int*)  d_in[0];
    const float* embed  = (const float*)d_in[1];
    const float* W_ih   = (const float*)d_in[2];
    const float* W_hh   = (const float*)d_in[3];
    const float* b_ih   = (const float*)d_in[4];
    const float* b_hh   = (const float*)d_in[5];
    const float* pred_W = (const float*)d_in[6];
    const float* pred_b = (const float*)d_in[7];
    float* out = (float*)d_out;

    cudaFuncSetAttribute(pe_hmma_kernel,   cudaFuncAttributeMaxDynamicSharedMemorySize, PROJ_SMEM);
    cudaFuncSetAttribute(scan_hmma_kernel, cudaFuncAttributeMaxDynamicSharedMemorySize, SCAN_SMEM);

    pe_hmma_kernel<<<NVPAD / 64, 128, PROJ_SMEM>>>(embed, W_ih, b_ih, b_hh);
    scan_hmma_kernel<<<128, 256, SCAN_SMEM>>>(x, W_ih, W_hh, b_ih, b_hh, pred_W);
    reduce2_kernel<<<NB, 1024>>>(pred_b, out);
}

// round 10
// speedup vs baseline: 24.9129x; 1.0371x over previous
#include <cuda_runtime.h>
#include <cuda_fp16.h>
#include <cstdint>

#define NB 4
#define NR 64
#define NC 64
#define NSEQ 16384
#define SLEN 32
#define HD 128
#define NV 30000
#define NVPAD 30080             // 470 * 64
#define PKW 136                 // fp16 pitch of weight/A tiles (272B, LDSM conflict-free)
#define TILE_B (128*PKW*2)      // 34816 bytes per 128x128 fp16 tile
#define TILE_A64 (64*PKW*2)     // 17408 bytes per 64x128 fp16 tile
#define TILE_U4 (TILE_B/16)     // 2176 uint4 per 128-row tile

// ---------------- device scratch ----------------
__device__ float g_PE[(size_t)NVPAD * HD];     // 15.4 MB: embed @ Wi1^T + b1 (L2-resident)
__device__ uint4 g_Wt[4][TILE_U4];             // fp16 pitched tiles: Wi1, Wh1, Wi2, Wh2
__device__ float g_u[NSEQ];
__device__ float g_v[NSEQ];

// ================= helpers =================
__device__ __forceinline__ uint32_t smem_u32(const void* p) {
    uint32_t a;
    asm("{ .reg .u64 t; cvta.to.shared.u64 t, %1; cvt.u32.u64 %0, t; }" : "=r"(a) : "l"(p));
    return a;
}
__device__ __forceinline__ void ldsm_x4(uint32_t* r, uint32_t addr) {
    asm volatile("ldmatrix.sync.aligned.m8n8.x4.shared.b16 {%0,%1,%2,%3}, [%4];"
        : "=r"(r[0]), "=r"(r[1]), "=r"(r[2]), "=r"(r[3]) : "r"(addr));
}
__device__ __forceinline__ void mma_op(float* d, const uint32_t* a, uint32_t b0, uint32_t b1) {
    asm volatile("mma.sync.aligned.m16n8k16.row.col.f32.f16.f16.f32 "
        "{%0,%1,%2,%3}, {%4,%5,%6,%7}, {%8,%9}, {%0,%1,%2,%3};"
        : "+f"(d[0]), "+f"(d[1]), "+f"(d[2]), "+f"(d[3])
        : "r"(a[0]), "r"(a[1]), "r"(a[2]), "r"(a[3]), "r"(b0), "r"(b1));
}
// split (f0,f1) into fp16 hi pair + residual lo pair
__device__ __forceinline__ void split2h(float f0, float f1, uint32_t& hi, uint32_t& lo) {
    __half h0 = __float2half_rn(f0), h1 = __float2half_rn(f1);
    float l0 = f0 - __half2float(h0), l1 = f1 - __half2float(h1);
    __half2 hp = __halves2half2(h0, h1);
    __half2 lp = __halves2half2(__float2half_rn(l0), __float2half_rn(l1));
    hi = *reinterpret_cast<uint32_t*>(&hp);
    lo = *reinterpret_cast<uint32_t*>(&lp);
}

// Dual-A pass: D += (A0 + A1) x B — B fragments loaded ONCE
__device__ __forceinline__ void mma_pass2(float (*d)[4], const uint32_t* a0, const uint32_t* a1,
                                          uint32_t wb, int lrowB, int lkofB)
{
#pragma unroll
    for (int kc = 0; kc < 8; kc++) {
#pragma unroll
        for (int half = 0; half < 2; half++) {
            uint32_t b[16];
#pragma unroll
            for (int q = 0; q < 4; q++) {
                int ntp = half * 4 + q;
                ldsm_x4(b + 4 * q, wb + (uint32_t)(((ntp * 16 + lrowB) * PKW + kc * 16 + lkofB) * 2));
            }
#pragma unroll
            for (int q = 0; q < 4; q++) {
                int ntp = half * 4 + q;
                mma_op(d[2 * ntp],     a0 + 4 * kc, b[4 * q],     b[4 * q + 1]);
                mma_op(d[2 * ntp + 1], a0 + 4 * kc, b[4 * q + 2], b[4 * q + 3]);
                mma_op(d[2 * ntp],     a1 + 4 * kc, b[4 * q],     b[4 * q + 1]);
                mma_op(d[2 * ntp + 1], a1 + 4 * kc, b[4 * q + 2], b[4 * q + 3]);
            }
        }
    }
}

// =========================================================================
// Kernel 0 (prep): convert the 4 weight matrices to fp16 pitched tiles.
// tiles: [0]=Wi1, [1]=Wh1, [2]=Wi2, [3]=Wh2
// =========================================================================
__global__ void __launch_bounds__(256, 8) prep_kernel(
    const float* __restrict__ W_ih, const float* __restrict__ W_hh)
{
    int idx = blockIdx.x * 256 + threadIdx.x;
    if (idx >= 4 * 16384) return;
    int tile = idx >> 14, i = idx & 16383;
    int n = i >> 7, k = i & 127;
    const float* src = (tile == 0) ? W_ih : (tile == 1) ? W_hh
                     : (tile == 2) ? (W_ih + 16384) : (W_hh + 16384);
    reinterpret_cast<__half*>(g_Wt[tile])[n * PKW + k] = __float2half_rn(src[i]);
}

// =========================================================================
// Kernel 1 (PE): PE[v][h] = embed[v] @ Wi1^T + (bi1+bh1)
// 470 CTAs x 128 thr, 64-row tiles, 3 CTAs/SM; weights copied (no cvt).
// =========================================================================
#define P_AHI 0
#define P_ALO TILE_A64
#define P_B   (2*TILE_A64)
#define P_B1  (2*TILE_A64 + TILE_B)
#define PROJ_SMEM (2*TILE_A64 + TILE_B + 512)

__global__ void __launch_bounds__(128, 3) pe_hmma_kernel(
    const float* __restrict__ embed,
    const float* __restrict__ b_ih, const float* __restrict__ b_hh)
{
    extern __shared__ char smem[];
    const int tid = threadIdx.x;
    const int l = tid & 31, wid = tid >> 5;
    uint32_t sb = smem_u32(smem);

    const int vbase = blockIdx.x * 64;

    // vectorized copy of pre-converted Wi1 tile
    {
        uint4* wdst = (uint4*)(smem + P_B);
        for (int i = tid; i < TILE_U4; i += 128) wdst[i] = g_Wt[0][i];
    }
    ((float*)(smem + P_B1))[tid] = b_ih[tid] + b_hh[tid];
    const float* b1s = (const float*)(smem + P_B1);

    // A tile = 64 consecutive vocab embedding rows (guarded), fp16 hi/lo
    for (int i = tid; i < 64 * 32; i += 128) {
        int r = i >> 5, c = i & 31;
        int vr = vbase + r; if (vr >= NV) vr = NV - 1;
        float4 v = ((const float4*)embed)[(size_t)vr * 32 + c];
        uint32_t h01, l01, h23, l23;
        split2h(v.x, v.y, h01, l01);
        split2h(v.z, v.w, h23, l23);
        uint32_t off = (uint32_t)(r * PKW + 4 * c) * 2;
        *(uint2*)(smem + P_AHI + off) = make_uint2(h01, h23);
        *(uint2*)(smem + P_ALO + off) = make_uint2(l01, l23);
    }
    __syncthreads();

    const int mrow = wid * 16;
    const int lrowB = ((l >> 4) & 1) * 8 + (l & 7);
    const int lkofB = 8 * ((l >> 3) & 1);
    const int lrowA = ((l >> 3) & 1) * 8 + (l & 7);
    const int lkofA = 8 * ((l >> 4) & 1);
    const int g = l >> 2, c2 = (l & 3) * 2;

    float d[16][4];
#pragma unroll
    for (int j = 0; j < 16; j++)
#pragma unroll
        for (int q = 0; q < 4; q++) d[j][q] = 0.f;

    // fused 2-mult pass: B loaded once, A = Ahi + Alo
#pragma unroll
    for (int kc = 0; kc < 8; kc++) {
        uint32_t ah[4], al[4];
        uint32_t aoff = (uint32_t)(((mrow + lrowA) * PKW + kc * 16 + lkofA) * 2);
        ldsm_x4(ah, sb + P_AHI + aoff);
        ldsm_x4(al, sb + P_ALO + aoff);
#pragma unroll
        for (int half = 0; half < 2; half++) {
            uint32_t b[16];
#pragma unroll
            for (int q = 0; q < 4; q++) {
                int ntp = half * 4 + q;
                ldsm_x4(b + 4 * q, sb + P_B + (uint32_t)(((ntp * 16 + lrowB) * PKW + kc * 16 + lkofB) * 2));
            }
#pragma unroll
            for (int q = 0; q < 4; q++) {
                int ntp = half * 4 + q;
                mma_op(d[2 * ntp],     ah, b[4 * q],     b[4 * q + 1]);
                mma_op(d[2 * ntp + 1], ah, b[4 * q + 2], b[4 * q + 3]);
                mma_op(d[2 * ntp],     al, b[4 * q],     b[4 * q + 1]);
                mma_op(d[2 * ntp + 1], al, b[4 * q + 2], b[4 * q + 3]);
            }
        }
    }

    // epilogue: + bias, store to g_PE
    int row0 = vbase + mrow + g;
#pragma unroll
    for (int j = 0; j < 16; j++) {
        float2 bb = *(const float2*)(b1s + 8 * j + c2);
        float* o0 = g_PE + (size_t)row0 * HD + 8 * j + c2;
        *(float2*)o0 = make_float2(d[j][0] + bb.x, d[j][1] + bb.y);
        *(float2*)(o0 + 8 * HD) = make_float2(d[j][2] + bb.x, d[j][3] + bb.y);
    }
}

// =========================================================================
// Kernel 2 (scan): persistent register-fragment RNN, fp16 h-split (2-mult),
// single-fp16 weights, fused u/v head. 128 CTAs x 256 thr.
// =========================================================================
#define S_W1  0
#define S_WI  TILE_B
#define S_W2  (2*TILE_B)
#define S_B2  (3*TILE_B)
#define S_PW  (3*TILE_B + 512)
#define SCAN_SMEM (3*TILE_B + 512 + 1024)

__global__ void __launch_bounds__(256, 1) scan_hmma_kernel(
    const int* __restrict__ x,
    const float* __restrict__ b_ih, const float* __restrict__ b_hh,
    const float* __restrict__ pred_W)
{
    extern __shared__ char smem[];
    const int tid = threadIdx.x;
    const int l = tid & 31, wid = tid >> 5;
    uint32_t sb = smem_u32(smem);

    // vectorized copy of pre-converted Wh1 / Wi2 / Wh2 tiles
    {
        uint4* wdst = (uint4*)(smem + S_W1);
        for (int i = tid; i < 3 * TILE_U4; i += 256) {
            int t = i / TILE_U4, j = i - t * TILE_U4;
            wdst[t * TILE_U4 + j] = g_Wt[1 + t][j];
        }
    }
    if (tid < 128) ((float*)(smem + S_B2))[tid] = b_ih[128 + tid] + b_hh[128 + tid];
    if (tid < 256) ((float*)(smem + S_PW))[tid] = pred_W[tid];
    __syncthreads();

    const int lrowB = ((l >> 4) & 1) * 8 + (l & 7);
    const int lkofB = 8 * ((l >> 3) & 1);
    const int g = l >> 2, c2 = (l & 3) * 2;
    const int mrow = wid * 16;
    const size_t rowA = (size_t)(blockIdx.x * 128 + mrow + g);
    const float* b2s = (const float*)(smem + S_B2);
    const float* pw1 = (const float*)(smem + S_PW);
    const float* pw2 = pw1 + 128;

    const int* xa = x + rowA * SLEN;            // tokens of seq rowA
    const int* xb = x + (rowA + 8) * SLEN;      // tokens of seq rowA+8
    int tokA = xa[0], tokB = xb[0];

    uint32_t h1h[32], h1l[32], h2h[32], h2l[32];
#pragma unroll
    for (int i = 0; i < 32; i++) { h1h[i] = 0; h1l[i] = 0; h2h[i] = 0; h2l[i] = 0; }

    float d[16][4];
    float u_a = 0.f, v_a = 0.f, u_b = 0.f, v_b = 0.f;

#pragma unroll 1
    for (int t = 0; t < SLEN; t++) {
        // ---- D init = PE[token] (L2-resident gather; b1 folded into PE) ----
        const float* pa = g_PE + (size_t)tokA * HD;
        const float* pb = g_PE + (size_t)tokB * HD;
#pragma unroll
        for (int j = 0; j < 16; j++) {
            float2 v0 = *(const float2*)(pa + 8 * j + c2);
            float2 v1 = *(const float2*)(pb + 8 * j + c2);
            d[j][0] = v0.x; d[j][1] = v0.y; d[j][2] = v1.x; d[j][3] = v1.y;
        }
        if (t + 1 < SLEN) { tokA = xa[t + 1]; tokB = xb[t + 1]; }

        // ---- layer 1: D += (h1h + h1l) x Wh1 (one B stream) ----
        mma_pass2(d, h1h, h1l, sb + S_W1, lrowB, lkofB);

        // ---- epilogue 1: h1 = split(relu(D)) ----
#pragma unroll
        for (int kc = 0; kc < 8; kc++) {
            int j0 = 2 * kc, j1 = 2 * kc + 1;
            split2h(fmaxf(d[j0][0], 0.f), fmaxf(d[j0][1], 0.f), h1h[4*kc+0], h1l[4*kc+0]);
            split2h(fmaxf(d[j0][2], 0.f), fmaxf(d[j0][3], 0.f), h1h[4*kc+1], h1l[4*kc+1]);
            split2h(fmaxf(d[j1][0], 0.f), fmaxf(d[j1][1], 0.f), h1h[4*kc+2], h1l[4*kc+2]);
            split2h(fmaxf(d[j1][2], 0.f), fmaxf(d[j1][3], 0.f), h1h[4*kc+3], h1l[4*kc+3]);
        }

        // ---- layer 2: D = (h1h+h1l) x Wi2 + (h2h+h2l) x Wh2 ----
#pragma unroll
        for (int j = 0; j < 16; j++)
#pragma unroll
            for (int q = 0; q < 4; q++) d[j][q] = 0.f;
        mma_pass2(d, h1h, h1l, sb + S_WI, lrowB, lkofB);
        mma_pass2(d, h2h, h2l, sb + S_W2, lrowB, lkofB);

        // ---- epilogue 2: h2 = split(relu(D + b2)); fused u/v head at last t ----
#pragma unroll
        for (int kc = 0; kc < 8; kc++) {
            int j0 = 2 * kc, j1 = 2 * kc + 1;
            float2 bb0 = *(const float2*)(b2s + 8 * j0 + c2);
            float2 bb1 = *(const float2*)(b2s + 8 * j1 + c2);
            float f00 = fmaxf(d[j0][0] + bb0.x, 0.f), f01 = fmaxf(d[j0][1] + bb0.y, 0.f);
            float f02 = fmaxf(d[j0][2] + bb0.x, 0.f), f03 = fmaxf(d[j0][3] + bb0.y, 0.f);
            float f10 = fmaxf(d[j1][0] + bb1.x, 0.f), f11 = fmaxf(d[j1][1] + bb1.y, 0.f);
            float f12 = fmaxf(d[j1][2] + bb1.x, 0.f), f13 = fmaxf(d[j1][3] + bb1.y, 0.f);
            split2h(f00, f01, h2h[4*kc+0], h2l[4*kc+0]);
            split2h(f02, f03, h2h[4*kc+1], h2l[4*kc+1]);
            split2h(f10, f11, h2h[4*kc+2], h2l[4*kc+2]);
            split2h(f12, f13, h2h[4*kc+3], h2l[4*kc+3]);
            if (t == SLEN - 1) {
                int c0 = 8 * j0 + c2, c1 = 8 * j1 + c2;
                u_a += pw1[c0] * f00 + pw1[c0 + 1] * f01 + pw1[c1] * f10 + pw1[c1 + 1] * f11;
                u_b += pw1[c0] * f02 + pw1[c0 + 1] * f03 + pw1[c1] * f12 + pw1[c1 + 1] * f13;
                v_a += pw2[c0] * f00 + pw2[c0 + 1] * f01 + pw2[c1] * f10 + pw2[c1 + 1] * f11;
                v_b += pw2[c0] * f02 + pw2[c0 + 1] * f03 + pw2[c1] * f12 + pw2[c1 + 1] * f13;
            }
        }
    }

    // quad reduction over the 4 lanes sharing each row (c2 = 0,2,4,6)
#pragma unroll
    for (int o = 1; o <= 2; o <<= 1) {
        u_a += __shfl_xor_sync(0xffffffffu, u_a, o);
        u_b += __shfl_xor_sync(0xffffffffu, u_b, o);
        v_a += __shfl_xor_sync(0xffffffffu, v_a, o);
        v_b += __shfl_xor_sync(0xffffffffu, v_b, o);
    }
    if ((l & 3) == 0) {
        g_u[rowA] = u_a;     g_v[rowA] = v_a;
        g_u[rowA + 8] = u_b; g_v[rowA + 8] = v_b;
    }
}

// =========================================================================
// Kernel 3: out = u - 2v + rowsum(v) + colsum(v) + pred_b
// grid NB x 1024 thr; warp-per-row/col shuffle reductions; pitch-65 smem.
// =========================================================================
__global__ void __launch_bounds__(1024, 1) reduce2_kernel(
    const float* __restrict__ pred_b, float* __restrict__ out)
{
    __shared__ float vs[64 * 65];
    __shared__ float RS[64], CS[64];
    const int b = blockIdx.x, tid = threadIdx.x;
    const int w = tid >> 5, l = tid & 31;

    for (int i = tid; i < 4096; i += 1024)
        vs[(i >> 6) * 65 + (i & 63)] = g_v[b * 4096 + i];
    __syncthreads();

    // row sums: warp w -> rows w, w+32
    float r0 = vs[w * 65 + l] + vs[w * 65 + l + 32];
    float r1 = vs[(w + 32) * 65 + l] + vs[(w + 32) * 65 + l + 32];
    // col sums: warp w -> cols w, w+32 (pitch 65 => conflict-free)
    float q0 = vs[l * 65 + w] + vs[(l + 32) * 65 + w];
    float q1 = vs[l * 65 + w + 32] + vs[(l + 32) * 65 + w + 32];
#pragma unroll
    for (int o = 16; o; o >>= 1) {
        r0 += __shfl_xor_sync(0xffffffffu, r0, o);
        r1 += __shfl_xor_sync(0xffffffffu, r1, o);
        q0 += __shfl_xor_sync(0xffffffffu, q0, o);
        q1 += __shfl_xor_sync(0xffffffffu, q1, o);
    }
    if (l == 0) { RS[w] = r0; RS[w + 32] = r1; CS[w] = q0; CS[w + 32] = q1; }
    __syncthreads();

    float pb = pred_b[0];
    for (int i = tid; i < 4096; i += 1024) {
        int r = i >> 6, c = i & 63;
        out[b * 4096 + i] =
            g_u[b * 4096 + i] - 2.f * vs[r * 65 + c] + RS[r] + CS[c] + pb;
    }
}

// =========================================================================
extern "C" void kernel_launch(void* const* d_in, const int* in_sizes, int n_in,
                              void* d_out, int out_size)
{
    const int*   x      = (const int*)  d_in[0];
    const float* embed  = (const float*)d_in[1];
    const float* W_ih   = (const float*)d_in[2];
    const float* W_hh   = (const float*)d_in[3];
    const float* b_ih   = (const float*)d_in[4];
    const float* b_hh   = (const float*)d_in[5];
    const float* pred_W = (const float*)d_in[6];
    const float* pred_b = (const float*)d_in[7];
    float* out = (float*)d_out;

    cudaFuncSetAttribute(pe_hmma_kernel,   cudaFuncAttributeMaxDynamicSharedMemorySize, PROJ_SMEM);
    cudaFuncSetAttribute(scan_hmma_kernel, cudaFuncAttributeMaxDynamicSharedMemorySize, SCAN_SMEM);

    prep_kernel<<<256, 256>>>(W_ih, W_hh);
    pe_hmma_kernel<<<NVPAD / 64, 128, PROJ_SMEM>>>(embed, b_ih, b_hh);
    scan_hmma_kernel<<<128, 256, SCAN_SMEM>>>(x, b_ih, b_hh, pred_W);
    reduce2_kernel<<<NB, 1024>>>(pred_b, out);
}

// round 11
// speedup vs baseline: 35.9934x; 1.4448x over previous
#include <cuda_runtime.h>
#include <cuda_fp16.h>
#include <cstdint>

#define NB 4
#define NR 64
#define NC 64
#define NSEQ 16384
#define SLEN 32
#define HD 128
#define NV 30000
#define NVPAD 30080             // 470 * 64
#define PKW 136                 // fp16 pitch of weight/A tiles (272B, LDSM conflict-free)
#define TILE_B (128*PKW*2)      // 34816 bytes per 128x128 fp16 tile
#define TILE_A64 (64*PKW*2)     // 17408 bytes per 64x128 fp16 tile
#define TILE_U4 (TILE_B/16)     // 2176 uint4 per 128-row tile

// ---------------- device scratch ----------------
__device__ float g_PE[(size_t)NVPAD * HD];     // 15.4 MB: embed @ Wi1^T + b1 (L2-resident)
__device__ uint4 g_Wt[4][TILE_U4];             // fp16 pitched tiles: Wi1, Wh1, Wi2, Wh2
__device__ float g_u[NSEQ];
__device__ float g_v[NSEQ];

// ================= helpers =================
__device__ __forceinline__ uint32_t smem_u32(const void* p) {
    uint32_t a;
    asm("{ .reg .u64 t; cvta.to.shared.u64 t, %1; cvt.u32.u64 %0, t; }" : "=r"(a) : "l"(p));
    return a;
}
__device__ __forceinline__ void ldsm_x4(uint32_t* r, uint32_t addr) {
    asm volatile("ldmatrix.sync.aligned.m8n8.x4.shared.b16 {%0,%1,%2,%3}, [%4];"
        : "=r"(r[0]), "=r"(r[1]), "=r"(r[2]), "=r"(r[3]) : "r"(addr));
}
__device__ __forceinline__ void mma_op(float* d, const uint32_t* a, uint32_t b0, uint32_t b1) {
    asm volatile("mma.sync.aligned.m16n8k16.row.col.f32.f16.f16.f32 "
        "{%0,%1,%2,%3}, {%4,%5,%6,%7}, {%8,%9}, {%0,%1,%2,%3};"
        : "+f"(d[0]), "+f"(d[1]), "+f"(d[2]), "+f"(d[3])
        : "r"(a[0]), "r"(a[1]), "r"(a[2]), "r"(a[3]), "r"(b0), "r"(b1));
}
// split (f0,f1) into fp16 hi pair + residual lo pair
__device__ __forceinline__ void split2h(float f0, float f1, uint32_t& hi, uint32_t& lo) {
    __half h0 = __float2half_rn(f0), h1 = __float2half_rn(f1);
    float l0 = f0 - __half2float(h0), l1 = f1 - __half2float(h1);
    __half2 hp = __halves2half2(h0, h1);
    __half2 lp = __halves2half2(__float2half_rn(l0), __float2half_rn(l1));
    hi = *reinterpret_cast<uint32_t*>(&hp);
    lo = *reinterpret_cast<uint32_t*>(&lp);
}
// pack (f0,f1) into a single fp16 pair
__device__ __forceinline__ uint32_t pack2h(float f0, float f1) {
    __half2 hp = __halves2half2(__float2half_rn(f0), __float2half_rn(f1));
    return *reinterpret_cast<uint32_t*>(&hp);
}

// Single-A pass: D += A x B(smem tile at wb)
__device__ __forceinline__ void mma_pass1(float (*d)[4], const uint32_t* a,
                                          uint32_t wb, int lrowB, int lkofB)
{
#pragma unroll
    for (int kc = 0; kc < 8; kc++) {
#pragma unroll
        for (int half = 0; half < 2; half++) {
            uint32_t b[16];
#pragma unroll
            for (int q = 0; q < 4; q++) {
                int ntp = half * 4 + q;
                ldsm_x4(b + 4 * q, wb + (uint32_t)(((ntp * 16 + lrowB) * PKW + kc * 16 + lkofB) * 2));
            }
#pragma unroll
            for (int q = 0; q < 4; q++) {
                int ntp = half * 4 + q;
                mma_op(d[2 * ntp],     a + 4 * kc, b[4 * q],     b[4 * q + 1]);
                mma_op(d[2 * ntp + 1], a + 4 * kc, b[4 * q + 2], b[4 * q + 3]);
            }
        }
    }
}

// =========================================================================
// Kernel 0 (prep): convert the 4 weight matrices to fp16 pitched tiles.
// tiles: [0]=Wi1, [1]=Wh1, [2]=Wi2, [3]=Wh2
// =========================================================================
__global__ void __launch_bounds__(256, 8) prep_kernel(
    const float* __restrict__ W_ih, const float* __restrict__ W_hh)
{
    int idx = blockIdx.x * 256 + threadIdx.x;
    if (idx >= 4 * 16384) return;
    int tile = idx >> 14, i = idx & 16383;
    int n = i >> 7, k = i & 127;
    const float* src = (tile == 0) ? W_ih : (tile == 1) ? W_hh
                     : (tile == 2) ? (W_ih + 16384) : (W_hh + 16384);
    reinterpret_cast<__half*>(g_Wt[tile])[n * PKW + k] = __float2half_rn(src[i]);
}

// =========================================================================
// Kernel 1 (PE): PE[v][h] = embed[v] @ Wi1^T + (bi1+bh1)
// 470 CTAs x 128 thr, 64-row tiles, 3 CTAs/SM; embed split hi/lo (2-mult).
// =========================================================================
#define P_AHI 0
#define P_ALO TILE_A64
#define P_B   (2*TILE_A64)
#define P_B1  (2*TILE_A64 + TILE_B)
#define PROJ_SMEM (2*TILE_A64 + TILE_B + 512)

__global__ void __launch_bounds__(128, 3) pe_hmma_kernel(
    const float* __restrict__ embed,
    const float* __restrict__ b_ih, const float* __restrict__ b_hh)
{
    extern __shared__ char smem[];
    const int tid = threadIdx.x;
    const int l = tid & 31, wid = tid >> 5;
    uint32_t sb = smem_u32(smem);

    const int vbase = blockIdx.x * 64;

    // vectorized copy of pre-converted Wi1 tile
    {
        uint4* wdst = (uint4*)(smem + P_B);
        for (int i = tid; i < TILE_U4; i += 128) wdst[i] = g_Wt[0][i];
    }
    ((float*)(smem + P_B1))[tid] = b_ih[tid] + b_hh[tid];
    const float* b1s = (const float*)(smem + P_B1);

    // A tile = 64 consecutive vocab embedding rows (guarded), fp16 hi/lo
    for (int i = tid; i < 64 * 32; i += 128) {
        int r = i >> 5, c = i & 31;
        int vr = vbase + r; if (vr >= NV) vr = NV - 1;
        float4 v = ((const float4*)embed)[(size_t)vr * 32 + c];
        uint32_t h01, l01, h23, l23;
        split2h(v.x, v.y, h01, l01);
        split2h(v.z, v.w, h23, l23);
        uint32_t off = (uint32_t)(r * PKW + 4 * c) * 2;
        *(uint2*)(smem + P_AHI + off) = make_uint2(h01, h23);
        *(uint2*)(smem + P_ALO + off) = make_uint2(l01, l23);
    }
    __syncthreads();

    const int mrow = wid * 16;
    const int lrowB = ((l >> 4) & 1) * 8 + (l & 7);
    const int lkofB = 8 * ((l >> 3) & 1);
    const int lrowA = ((l >> 3) & 1) * 8 + (l & 7);
    const int lkofA = 8 * ((l >> 4) & 1);
    const int g = l >> 2, c2 = (l & 3) * 2;

    float d[16][4];
#pragma unroll
    for (int j = 0; j < 16; j++)
#pragma unroll
        for (int q = 0; q < 4; q++) d[j][q] = 0.f;

    // fused 2-mult pass: B loaded once, A = Ahi + Alo
#pragma unroll
    for (int kc = 0; kc < 8; kc++) {
        uint32_t ah[4], al[4];
        uint32_t aoff = (uint32_t)(((mrow + lrowA) * PKW + kc * 16 + lkofA) * 2);
        ldsm_x4(ah, sb + P_AHI + aoff);
        ldsm_x4(al, sb + P_ALO + aoff);
#pragma unroll
        for (int half = 0; half < 2; half++) {
            uint32_t b[16];
#pragma unroll
            for (int q = 0; q < 4; q++) {
                int ntp = half * 4 + q;
                ldsm_x4(b + 4 * q, sb + P_B + (uint32_t)(((ntp * 16 + lrowB) * PKW + kc * 16 + lkofB) * 2));
            }
#pragma unroll
            for (int q = 0; q < 4; q++) {
                int ntp = half * 4 + q;
                mma_op(d[2 * ntp],     ah, b[4 * q],     b[4 * q + 1]);
                mma_op(d[2 * ntp + 1], ah, b[4 * q + 2], b[4 * q + 3]);
                mma_op(d[2 * ntp],     al, b[4 * q],     b[4 * q + 1]);
                mma_op(d[2 * ntp + 1], al, b[4 * q + 2], b[4 * q + 3]);
            }
        }
    }

    // epilogue: + bias, store to g_PE
    int row0 = vbase + mrow + g;
#pragma unroll
    for (int j = 0; j < 16; j++) {
        float2 bb = *(const float2*)(b1s + 8 * j + c2);
        float* o0 = g_PE + (size_t)row0 * HD + 8 * j + c2;
        *(float2*)o0 = make_float2(d[j][0] + bb.x, d[j][1] + bb.y);
        *(float2*)(o0 + 8 * HD) = make_float2(d[j][2] + bb.x, d[j][3] + bb.y);
    }
}

// =========================================================================
// Kernel 2 (scan): persistent register-fragment RNN, single-fp16 states
// and weights (3 tile-mults/step), fused u/v head. 128 CTAs x 256 thr.
// =========================================================================
#define S_W1  0
#define S_WI  TILE_B
#define S_W2  (2*TILE_B)
#define S_B2  (3*TILE_B)
#define S_PW  (3*TILE_B + 512)
#define SCAN_SMEM (3*TILE_B + 512 + 1024)

__global__ void __launch_bounds__(256, 1) scan_hmma_kernel(
    const int* __restrict__ x,
    const float* __restrict__ b_ih, const float* __restrict__ b_hh,
    const float* __restrict__ pred_W)
{
    extern __shared__ char smem[];
    const int tid = threadIdx.x;
    const int l = tid & 31, wid = tid >> 5;
    uint32_t sb = smem_u32(smem);

    // vectorized copy of pre-converted Wh1 / Wi2 / Wh2 tiles
    {
        uint4* wdst = (uint4*)(smem + S_W1);
        for (int i = tid; i < 3 * TILE_U4; i += 256) {
            int t = i / TILE_U4, j = i - t * TILE_U4;
            wdst[t * TILE_U4 + j] = g_Wt[1 + t][j];
        }
    }
    if (tid < 128) ((float*)(smem + S_B2))[tid] = b_ih[128 + tid] + b_hh[128 + tid];
    if (tid < 256) ((float*)(smem + S_PW))[tid] = pred_W[tid];
    __syncthreads();

    const int lrowB = ((l >> 4) & 1) * 8 + (l & 7);
    const int lkofB = 8 * ((l >> 3) & 1);
    const int g = l >> 2, c2 = (l & 3) * 2;
    const int mrow = wid * 16;
    const size_t rowA = (size_t)(blockIdx.x * 128 + mrow + g);
    const float* b2s = (const float*)(smem + S_B2);
    const float* pw1 = (const float*)(smem + S_PW);
    const float* pw2 = pw1 + 128;

    const int* xa = x + rowA * SLEN;            // tokens of seq rowA
    const int* xb = x + (rowA + 8) * SLEN;      // tokens of seq rowA+8
    int tokA = xa[0], tokB = xb[0];

    uint32_t h1h[32], h2h[32];
#pragma unroll
    for (int i = 0; i < 32; i++) { h1h[i] = 0; h2h[i] = 0; }

    float d[16][4];
    float u_a = 0.f, v_a = 0.f, u_b = 0.f, v_b = 0.f;

#pragma unroll 1
    for (int t = 0; t < SLEN; t++) {
        // ---- D init = PE[token] (L2-resident gather; b1 folded into PE) ----
        const float* pa = g_PE + (size_t)tokA * HD;
        const float* pb = g_PE + (size_t)tokB * HD;
#pragma unroll
        for (int j = 0; j < 16; j++) {
            float2 v0 = *(const float2*)(pa + 8 * j + c2);
            float2 v1 = *(const float2*)(pb + 8 * j + c2);
            d[j][0] = v0.x; d[j][1] = v0.y; d[j][2] = v1.x; d[j][3] = v1.y;
        }
        if (t + 1 < SLEN) { tokA = xa[t + 1]; tokB = xb[t + 1]; }

        // ---- layer 1: D += h1 x Wh1 ----
        mma_pass1(d, h1h, sb + S_W1, lrowB, lkofB);

        // ---- epilogue 1: h1 = fp16(relu(D)) ----
#pragma unroll
        for (int kc = 0; kc < 8; kc++) {
            int j0 = 2 * kc, j1 = 2 * kc + 1;
            h1h[4*kc+0] = pack2h(fmaxf(d[j0][0], 0.f), fmaxf(d[j0][1], 0.f));
            h1h[4*kc+1] = pack2h(fmaxf(d[j0][2], 0.f), fmaxf(d[j0][3], 0.f));
            h1h[4*kc+2] = pack2h(fmaxf(d[j1][0], 0.f), fmaxf(d[j1][1], 0.f));
            h1h[4*kc+3] = pack2h(fmaxf(d[j1][2], 0.f), fmaxf(d[j1][3], 0.f));
        }

        // ---- layer 2: D = h1 x Wi2 + h2 x Wh2 ----
#pragma unroll
        for (int j = 0; j < 16; j++)
#pragma unroll
            for (int q = 0; q < 4; q++) d[j][q] = 0.f;
        mma_pass1(d, h1h, sb + S_WI, lrowB, lkofB);
        mma_pass1(d, h2h, sb + S_W2, lrowB, lkofB);

        // ---- epilogue 2: h2 = fp16(relu(D + b2)); fused u/v head at last t ----
#pragma unroll
        for (int kc = 0; kc < 8; kc++) {
            int j0 = 2 * kc, j1 = 2 * kc + 1;
            float2 bb0 = *(const float2*)(b2s + 8 * j0 + c2);
            float2 bb1 = *(const float2*)(b2s + 8 * j1 + c2);
            float f00 = fmaxf(d[j0][0] + bb0.x, 0.f), f01 = fmaxf(d[j0][1] + bb0.y, 0.f);
            float f02 = fmaxf(d[j0][2] + bb0.x, 0.f), f03 = fmaxf(d[j0][3] + bb0.y, 0.f);
            float f10 = fmaxf(d[j1][0] + bb1.x, 0.f), f11 = fmaxf(d[j1][1] + bb1.y, 0.f);
            float f12 = fmaxf(d[j1][2] + bb1.x, 0.f), f13 = fmaxf(d[j1][3] + bb1.y, 0.f);
            h2h[4*kc+0] = pack2h(f00, f01);
            h2h[4*kc+1] = pack2h(f02, f03);
            h2h[4*kc+2] = pack2h(f10, f11);
            h2h[4*kc+3] = pack2h(f12, f13);
            if (t == SLEN - 1) {
                int c0 = 8 * j0 + c2, c1 = 8 * j1 + c2;
                u_a += pw1[c0] * f00 + pw1[c0 + 1] * f01 + pw1[c1] * f10 + pw1[c1 + 1] * f11;
                u_b += pw1[c0] * f02 + pw1[c0 + 1] * f03 + pw1[c1] * f12 + pw1[c1 + 1] * f13;
                v_a += pw2[c0] * f00 + pw2[c0 + 1] * f01 + pw2[c1] * f10 + pw2[c1 + 1] * f11;
                v_b += pw2[c0] * f02 + pw2[c0 + 1] * f03 + pw2[c1] * f12 + pw2[c1 + 1] * f13;
            }
        }
    }

    // quad reduction over the 4 lanes sharing each row (c2 = 0,2,4,6)
#pragma unroll
    for (int o = 1; o <= 2; o <<= 1) {
        u_a += __shfl_xor_sync(0xffffffffu, u_a, o);
        u_b += __shfl_xor_sync(0xffffffffu, u_b, o);
        v_a += __shfl_xor_sync(0xffffffffu, v_a, o);
        v_b += __shfl_xor_sync(0xffffffffu, v_b, o);
    }
    if ((l & 3) == 0) {
        g_u[rowA] = u_a;     g_v[rowA] = v_a;
        g_u[rowA + 8] = u_b; g_v[rowA + 8] = v_b;
    }
}

// =========================================================================
// Kernel 3: out = u - 2v + rowsum(v) + colsum(v) + pred_b
// grid NB x 1024 thr; warp-per-row/col shuffle reductions; pitch-65 smem.
// =========================================================================
__global__ void __launch_bounds__(1024, 1) reduce2_kernel(
    const float* __restrict__ pred_b, float* __restrict__ out)
{
    __shared__ float vs[64 * 65];
    __shared__ float RS[64], CS[64];
    const int b = blockIdx.x, tid = threadIdx.x;
    const int w = tid >> 5, l = tid & 31;

    for (int i = tid; i < 4096; i += 1024)
        vs[(i >> 6) * 65 + (i & 63)] = g_v[b * 4096 + i];
    __syncthreads();

    // row sums: warp w -> rows w, w+32
    float r0 = vs[w * 65 + l] + vs[w * 65 + l + 32];
    float r1 = vs[(w + 32) * 65 + l] + vs[(w + 32) * 65 + l + 32];
    // col sums: warp w -> cols w, w+32 (pitch 65 => conflict-free)
    float q0 = vs[l * 65 + w] + vs[(l + 32) * 65 + w];
    float q1 = vs[l * 65 + w + 32] + vs[(l + 32) * 65 + w + 32];
#pragma unroll
    for (int o = 16; o; o >>= 1) {
        r0 += __shfl_xor_sync(0xffffffffu, r0, o);
        r1 += __shfl_xor_sync(0xffffffffu, r1, o);
        q0 += __shfl_xor_sync(0xffffffffu, q0, o);
        q1 += __shfl_xor_sync(0xffffffffu, q1, o);
    }
    if (l == 0) { RS[w] = r0; RS[w + 32] = r1; CS[w] = q0; CS[w + 32] = q1; }
    __syncthreads();

    float pb = pred_b[0];
    for (int i = tid; i < 4096; i += 1024) {
        int r = i >> 6, c = i & 63;
        out[b * 4096 + i] =
            g_u[b * 4096 + i] - 2.f * vs[r * 65 + c] + RS[r] + CS[c] + pb;
    }
}

// =========================================================================
extern "C" void kernel_launch(void* const* d_in, const int* in_sizes, int n_in,
                              void* d_out, int out_size)
{
    const int*   x      = (const int*)  d_in[0];
    const float* embed  = (const float*)d_in[1];
    const float* W_ih   = (const float*)d_in[2];
    const float* W_hh   = (const float*)d_in[3];
    const float* b_ih   = (const float*)d_in[4];
    const float* b_hh   = (const float*)d_in[5];
    const float* pred_W = (const float*)d_in[6];
    const float* pred_b = (const float*)d_in[7];
    float* out = (float*)d_out;

    cudaFuncSetAttribute(pe_hmma_kernel,   cudaFuncAttributeMaxDynamicSharedMemorySize, PROJ_SMEM);
    cudaFuncSetAttribute(scan_hmma_kernel, cudaFuncAttributeMaxDynamicSharedMemorySize, SCAN_SMEM);

    prep_kernel<<<256, 256>>>(W_ih, W_hh);
    pe_hmma_kernel<<<NVPAD / 64, 128, PROJ_SMEM>>>(embed, b_ih, b_hh);
    scan_hmma_kernel<<<128, 256, SCAN_SMEM>>>(x, b_ih, b_hh, pred_W);
    reduce2_kernel<<<NB, 1024>>>(pred_b, out);
}